// round 4
// baseline (speedup 1.0000x reference)
#include <cuda_runtime.h>
#include <math.h>

#define NN 50000
#define EE 800000

__device__ float g_h[NN * 64];      // node latent state
__device__ float g_e[EE * 64];      // edge features
__device__ float g_recv[NN * 64];   // aggregated messages

typedef unsigned long long u64;

#define FMA2(d, a, b) asm("fma.rn.f32x2 %0, %1, %2, %0;" : "+l"(d) : "l"(a), "l"(b))

__device__ __forceinline__ float hadd2(u64 v) {
    float lo, hi;
    asm("mov.b64 {%0, %1}, %2;" : "=f"(lo), "=f"(hi) : "l"(v));
    return lo + hi;
}

// jax.nn.gelu (approximate=True) with exp-based tanh (~1e-7 accurate)
__device__ __forceinline__ float gelu_t(float x) {
    float y = 0.7978845608028654f * (x + 0.044715f * x * x * x);
    float e = __expf(2.0f * y);
    float th = 1.0f - __fdividef(2.0f, e + 1.0f);
    return 0.5f * x * (1.0f + th);
}

// ---------------------------------------------------------------------------
__global__ void embed_kernel(const float* __restrict__ nodes,
                             const float* __restrict__ w,
                             const float* __restrict__ b, int Nv) {
    int idx = blockIdx.x * blockDim.x + threadIdx.x;
    if (idx >= Nv * 64) return;
    int n = idx >> 6, j = idx & 63;
    float a = b[j];
#pragma unroll
    for (int k = 0; k < 7; k++) a += nodes[n * 7 + k] * w[k * 64 + j];
    g_h[idx] = a;
}

__global__ void zero_recv_kernel(int n) {
    int i = blockIdx.x * blockDim.x + threadIdx.x;
    if (i < n) g_recv[i] = 0.0f;
}

// ---------------------------------------------------------------------------
// Fused edge MLP. CTA tile = 32 edges. 8 warps = 4 edge-groups x 2 j-halves.
// Lane = (e2 in [0,4), j8 in [0,8)). Layer1: warp does 8 edges x 64 j.
// Weight LDS.128 = 8 distinct j x 4-way bcast = 1 wavefront (stride pad).
// W2P=132: w2t rows are length-128 in k (w2 is [128][64] transposed!).
// ---------------------------------------------------------------------------
template <int DIN, bool HAS_E>
__global__ __launch_bounds__(256, 1) void edge_kernel(
    const int* __restrict__ senders, const int* __restrict__ receivers,
    const float* __restrict__ gvec,
    const float* __restrict__ w1, const float* __restrict__ b1,
    const float* __restrict__ w2, const float* __restrict__ b2,
    int En, int write_e) {
    constexpr int DINP = DIN + 4;   // 212 / 148 : *4 mod 128 == 80
    constexpr int W2P = 132;        // k-stride >= 128; 528 B mod 128 == 16
    constexpr int HP = 132;
    constexpr int MB = 32;
    constexpr int NC = DIN / 4;     // float4 chunks per input row

    extern __shared__ float sm[];
    float* w1t = sm;                       // 128*DINP  [j][k]
    float* w2t = w1t + 128 * DINP;         // 64*W2P    [j][k], k<128
    float* b1s = w2t + 64 * W2P;           // 128
    float* b2s = b1s + 128;                // 64
    float* gs  = b2s + 64;                 // 16
    float* inb = gs + 16;                  // MB*DINP
    float* hid = inb + MB * DINP;          // MB*HP
    int* sidx  = (int*)(hid + MB * HP);    // 32 ints
    int* ridx  = sidx + 32;                // 32 ints

    int tid = threadIdx.x;
    for (int i = tid; i < DIN * 128; i += 256) {
        int k = i >> 7, j = i & 127;
        w1t[j * DINP + k] = w1[i];
    }
    for (int i = tid; i < 128 * 64; i += 256) {
        int k = i >> 6, j = i & 63;
        w2t[j * W2P + k] = w2[i];
    }
    if (tid < 128) b1s[tid] = b1[tid];
    else if (tid < 192) b2s[tid - 128] = b2[tid - 128];
    else if (tid < 208) gs[tid - 192] = gvec[tid - 192];
    __syncthreads();

    int w = tid >> 5, lane = tid & 31;
    int e2 = lane >> 3, j8 = lane & 7;
    int eg = w & 3, jh = w >> 2;

    int nIter = (En + MB - 1) / MB;
    for (int it = blockIdx.x; it < nIter; it += gridDim.x) {
        int ebase = it * MB;
        // ---- A: indices ----
        if (tid < 32) {
            int e = ebase + tid; if (e >= En) e = En - 1;
            sidx[tid] = senders[e];
        } else if (tid < 64) {
            int e = ebase + tid - 32; if (e >= En) e = En - 1;
            ridx[tid - 32] = receivers[e];
        }
        __syncthreads();
        // ---- B: gather inputs ----
        {
            const float4* hp = (const float4*)g_h;
            const float4* gp4 = (const float4*)gs;
            for (int c = tid; c < MB * NC; c += 256) {
                int m = c / NC, q = c - m * NC;
                float4 v;
                if (HAS_E) {
                    int e = ebase + m; if (e >= En) e = En - 1;
                    if (q < 16)      v = ((const float4*)g_e)[(size_t)e * 16 + q];
                    else if (q < 32) v = hp[(size_t)sidx[m] * 16 + (q - 16)];
                    else if (q < 48) v = hp[(size_t)ridx[m] * 16 + (q - 32)];
                    else             v = gp4[q - 48];
                } else {
                    if (q < 16)      v = hp[(size_t)sidx[m] * 16 + q];
                    else if (q < 32) v = hp[(size_t)ridx[m] * 16 + (q - 16)];
                    else             v = gp4[q - 32];
                }
                ((float4*)(inb + m * DINP))[q] = v;
            }
        }
        __syncthreads();
        // ---- C: layer 1 (8 edges x 64 j per warp) ----
        {
            const float* in0 = inb + (eg * 8 + e2) * DINP;
            const float* in1 = in0 + 4 * DINP;
            const float* wb = w1t + (64 * jh + j8) * DINP;
            u64 acc[2][8];
#pragma unroll
            for (int u = 0; u < 8; u++) { acc[0][u] = 0ull; acc[1][u] = 0ull; }
#pragma unroll 2
            for (int k4 = 0; k4 < DIN / 4; k4++) {
                ulonglong2 a0 = *(const ulonglong2*)(in0 + 4 * k4);
                ulonglong2 a1 = *(const ulonglong2*)(in1 + 4 * k4);
#pragma unroll
                for (int u = 0; u < 8; u++) {
                    ulonglong2 wv = *(const ulonglong2*)(wb + u * 8 * DINP + 4 * k4);
                    FMA2(acc[0][u], a0.x, wv.x);
                    FMA2(acc[1][u], a1.x, wv.x);
                    FMA2(acc[0][u], a0.y, wv.y);
                    FMA2(acc[1][u], a1.y, wv.y);
                }
            }
#pragma unroll
            for (int u = 0; u < 8; u++) {
                int j = 64 * jh + j8 + 8 * u;
                float bj = b1s[j];
                hid[(eg * 8 + e2) * HP + j]     = gelu_t(hadd2(acc[0][u]) + bj);
                hid[(eg * 8 + e2 + 4) * HP + j] = gelu_t(hadd2(acc[1][u]) + bj);
            }
        }
        __syncthreads();
        // ---- D: layer 2 (4 edges x 64 j2 per warp) + scatter ----
        {
            int me = w * 4 + e2;
            const float* hrow = hid + me * HP;
            const float* wb2 = w2t + j8 * W2P;
            u64 acc[8];
#pragma unroll
            for (int u = 0; u < 8; u++) acc[u] = 0ull;
#pragma unroll 2
            for (int k4 = 0; k4 < 32; k4++) {
                ulonglong2 a = *(const ulonglong2*)(hrow + 4 * k4);
#pragma unroll
                for (int u = 0; u < 8; u++) {
                    ulonglong2 wv = *(const ulonglong2*)(wb2 + u * 8 * W2P + 4 * k4);
                    FMA2(acc[u], a.x, wv.x);
                    FMA2(acc[u], a.y, wv.y);
                }
            }
            int eid = ebase + me;
            if (eid < En) {
                int rc = ridx[me];
#pragma unroll
                for (int u = 0; u < 8; u++) {
                    int j2 = j8 + 8 * u;
                    float o = hadd2(acc[u]) + b2s[j2];
                    if (write_e) g_e[(size_t)eid * 64 + j2] = o;
                    atomicAdd(&g_recv[(size_t)rc * 64 + j2], o);
                }
            }
        }
        __syncthreads();  // D reads hid & ridx; protect vs next iter A/B/C
    }
}

// ---------------------------------------------------------------------------
// Fused node MLP + residual + LayerNorm. Same tiling, DIN=144.
// ---------------------------------------------------------------------------
__global__ __launch_bounds__(256, 1) void node_kernel(
    const float* __restrict__ gvec,
    const float* __restrict__ w1, const float* __restrict__ b1,
    const float* __restrict__ w2, const float* __restrict__ b2,
    const float* __restrict__ lnsc, const float* __restrict__ lnbi, int Nv) {
    constexpr int DIN = 144, DINP = 148, W2P = 132, HP = 132, MB = 32, NC = 36;
    extern __shared__ float sm[];
    float* w1t = sm;
    float* w2t = w1t + 128 * DINP;
    float* b1s = w2t + 64 * W2P;
    float* b2s = b1s + 128;
    float* gs  = b2s + 64;
    float* lns = gs + 16;
    float* lnb = lns + 64;
    float* inb = lnb + 64;
    float* hid = inb + MB * DINP;

    int tid = threadIdx.x;
    for (int i = tid; i < DIN * 128; i += 256) {
        int k = i >> 7, j = i & 127;
        w1t[j * DINP + k] = w1[i];
    }
    for (int i = tid; i < 128 * 64; i += 256) {
        int k = i >> 6, j = i & 63;
        w2t[j * W2P + k] = w2[i];
    }
    if (tid < 128) b1s[tid] = b1[tid];
    else if (tid < 192) b2s[tid - 128] = b2[tid - 128];
    else if (tid < 208) gs[tid - 192] = gvec[tid - 192];
    for (int i = tid; i < 64; i += 256) { lns[i] = lnsc[i]; lnb[i] = lnbi[i]; }
    __syncthreads();

    int w = tid >> 5, lane = tid & 31;
    int e2 = lane >> 3, j8 = lane & 7;
    int eg = w & 3, jh = w >> 2;

    int nIter = (Nv + MB - 1) / MB;
    for (int it = blockIdx.x; it < nIter; it += gridDim.x) {
        int nbase = it * MB;
        // ---- gather ----
        {
            const float4* hp = (const float4*)g_h;
            const float4* rp = (const float4*)g_recv;
            const float4* gp4 = (const float4*)gs;
            for (int c = tid; c < MB * NC; c += 256) {
                int m = c / NC, q = c - m * NC;
                int nid = nbase + m; if (nid >= Nv) nid = Nv - 1;
                float4 v;
                if (q < 16)      v = hp[(size_t)nid * 16 + q];
                else if (q < 32) v = rp[(size_t)nid * 16 + (q - 16)];
                else             v = gp4[q - 32];
                ((float4*)(inb + m * DINP))[q] = v;
            }
        }
        __syncthreads();
        // ---- layer 1 ----
        {
            const float* in0 = inb + (eg * 8 + e2) * DINP;
            const float* in1 = in0 + 4 * DINP;
            const float* wb = w1t + (64 * jh + j8) * DINP;
            u64 acc[2][8];
#pragma unroll
            for (int u = 0; u < 8; u++) { acc[0][u] = 0ull; acc[1][u] = 0ull; }
#pragma unroll 2
            for (int k4 = 0; k4 < DIN / 4; k4++) {
                ulonglong2 a0 = *(const ulonglong2*)(in0 + 4 * k4);
                ulonglong2 a1 = *(const ulonglong2*)(in1 + 4 * k4);
#pragma unroll
                for (int u = 0; u < 8; u++) {
                    ulonglong2 wv = *(const ulonglong2*)(wb + u * 8 * DINP + 4 * k4);
                    FMA2(acc[0][u], a0.x, wv.x);
                    FMA2(acc[1][u], a1.x, wv.x);
                    FMA2(acc[0][u], a0.y, wv.y);
                    FMA2(acc[1][u], a1.y, wv.y);
                }
            }
#pragma unroll
            for (int u = 0; u < 8; u++) {
                int j = 64 * jh + j8 + 8 * u;
                float bj = b1s[j];
                hid[(eg * 8 + e2) * HP + j]     = gelu_t(hadd2(acc[0][u]) + bj);
                hid[(eg * 8 + e2 + 4) * HP + j] = gelu_t(hadd2(acc[1][u]) + bj);
            }
        }
        __syncthreads();
        // ---- layer 2 + residual + LayerNorm ----
        {
            int me = w * 4 + e2;
            int nid = nbase + me;
            const float* hrow = hid + me * HP;
            const float* wb2 = w2t + j8 * W2P;
            u64 acc[8];
#pragma unroll
            for (int u = 0; u < 8; u++) acc[u] = 0ull;
#pragma unroll 2
            for (int k4 = 0; k4 < 32; k4++) {
                ulonglong2 a = *(const ulonglong2*)(hrow + 4 * k4);
#pragma unroll
                for (int u = 0; u < 8; u++) {
                    ulonglong2 wv = *(const ulonglong2*)(wb2 + u * 8 * W2P + 4 * k4);
                    FMA2(acc[u], a.x, wv.x);
                    FMA2(acc[u], a.y, wv.y);
                }
            }
            float x[8];
            float s = 0.0f, q = 0.0f;
#pragma unroll
            for (int u = 0; u < 8; u++) {
                int j2 = j8 + 8 * u;
                x[u] = inb[me * DINP + j2] + hadd2(acc[u]) + b2s[j2];
                s += x[u];
                q += x[u] * x[u];
            }
#pragma unroll
            for (int d = 1; d <= 4; d <<= 1) {
                s += __shfl_xor_sync(0xffffffffu, s, d);
                q += __shfl_xor_sync(0xffffffffu, q, d);
            }
            float mu = s * (1.0f / 64.0f);
            float var = q * (1.0f / 64.0f) - mu * mu;
            float inv = rsqrtf(var + 1e-6f);
            if (nid < Nv) {
#pragma unroll
                for (int u = 0; u < 8; u++) {
                    int j2 = j8 + 8 * u;
                    g_h[(size_t)nid * 64 + j2] =
                        (x[u] - mu) * inv * lns[j2] + lnb[j2];
                }
            }
        }
        __syncthreads();  // layer2 reads inb (residual); protect vs next gather
    }
}

// ---------------------------------------------------------------------------
__global__ void decode_kernel(const float* __restrict__ dec_w,
                              const float* __restrict__ dec_b,
                              float* __restrict__ out, int Nv) {
    int gwarp = (blockIdx.x * blockDim.x + threadIdx.x) >> 5;
    int lane = threadIdx.x & 31;
    int nWarps = (gridDim.x * blockDim.x) >> 5;
    for (int n = gwarp; n < Nv; n += nWarps) {
        float h0 = g_h[n * 64 + lane];
        float h1 = g_h[n * 64 + 32 + lane];
        float p[7];
#pragma unroll
        for (int k = 0; k < 7; k++)
            p[k] = h0 * dec_w[lane * 7 + k] + h1 * dec_w[(lane + 32) * 7 + k];
#pragma unroll
        for (int k = 0; k < 7; k++)
#pragma unroll
            for (int d = 16; d; d >>= 1) p[k] += __shfl_xor_sync(0xffffffffu, p[k], d);
        if (lane < 7) out[n * 7 + lane] = p[lane] + dec_b[lane];
    }
}

// ---------------------------------------------------------------------------
extern "C" void kernel_launch(void* const* d_in, const int* in_sizes, int n_in,
                              void* d_out, int out_size) {
    const float* nodes   = (const float*)d_in[0];
    const int*   senders = (const int*)d_in[1];
    const int*   recvrs  = (const int*)d_in[2];
    const float* g       = (const float*)d_in[3];
    const float* embed_w = (const float*)d_in[4];
    const float* embed_b = (const float*)d_in[5];
    const float* ew1f    = (const float*)d_in[6];
    const float* ew1r    = (const float*)d_in[7];
    const float* eb1     = (const float*)d_in[8];
    const float* ew2     = (const float*)d_in[9];
    const float* eb2     = (const float*)d_in[10];
    const float* nw1     = (const float*)d_in[11];
    const float* nb1     = (const float*)d_in[12];
    const float* nw2     = (const float*)d_in[13];
    const float* nb2     = (const float*)d_in[14];
    const float* lnsc    = (const float*)d_in[15];
    const float* lnbi    = (const float*)d_in[16];
    const float* dec_w   = (const float*)d_in[17];
    const float* dec_b   = (const float*)d_in[18];
    float* out = (float*)d_out;

    int En = in_sizes[1];
    int Nv = in_sizes[0] / 7;

    // smem bytes computed from exact layouts (W2P=132 fix)
    size_t sm_e0 = (size_t)(128 * 148 + 64 * 132 + 128 + 64 + 16 + 32 * 148 + 32 * 132 + 64) * 4;
    size_t sm_e1 = (size_t)(128 * 212 + 64 * 132 + 128 + 64 + 16 + 32 * 212 + 32 * 132 + 64) * 4;
    size_t sm_n  = (size_t)(128 * 148 + 64 * 132 + 128 + 64 + 16 + 64 + 64 + 32 * 148 + 32 * 132) * 4;

    cudaFuncSetAttribute(edge_kernel<144, false>,
                         cudaFuncAttributeMaxDynamicSharedMemorySize, (int)sm_e0);
    cudaFuncSetAttribute(edge_kernel<208, true>,
                         cudaFuncAttributeMaxDynamicSharedMemorySize, (int)sm_e1);
    cudaFuncSetAttribute(node_kernel,
                         cudaFuncAttributeMaxDynamicSharedMemorySize, (int)sm_n);

    const int GRID = 148;  // persistent, 1 CTA/SM

    embed_kernel<<<(Nv * 64 + 255) / 256, 256>>>(nodes, embed_w, embed_b, Nv);

    for (int t = 0; t < 3; t++) {
        zero_recv_kernel<<<(Nv * 64 + 255) / 256, 256>>>(Nv * 64);
        if (t == 0) {
            edge_kernel<144, false><<<GRID, 256, sm_e0>>>(
                senders, recvrs, g, ew1f, eb1, ew2, eb2, En, 1);
        } else {
            edge_kernel<208, true><<<GRID, 256, sm_e1>>>(
                senders, recvrs, g,
                ew1r + (size_t)(t - 1) * 208 * 128,
                eb1 + t * 128, ew2 + (size_t)t * 128 * 64, eb2 + t * 64,
                En, (t == 2) ? 0 : 1);
        }
        node_kernel<<<GRID, 256, sm_n>>>(
            g, nw1 + (size_t)t * 144 * 128, nb1 + t * 128,
            nw2 + (size_t)t * 128 * 64, nb2 + t * 64,
            lnsc + t * 64, lnbi + t * 64, Nv);
    }

    decode_kernel<<<208, 256>>>(dec_w, dec_b, out, Nv);
}

// round 5
// speedup vs baseline: 1.1473x; 1.1473x over previous
#include <cuda_runtime.h>
#include <math.h>

#define NN 50000
#define EE 800000

__device__ float g_h[NN * 64];
__device__ float g_e[EE * 64];
__device__ float g_recv[NN * 64];

typedef unsigned long long u64;

#define FMA2(d, a, b) asm("fma.rn.f32x2 %0, %1, %2, %0;" : "+l"(d) : "l"(a), "l"(b))
#define PACK2(d, lo, hi) asm("mov.b64 %0, {%1, %2};" : "=l"(d) : "f"(lo), "f"(hi))

__device__ __forceinline__ float hadd2(u64 v) {
    float lo, hi;
    asm("mov.b64 {%0, %1}, %2;" : "=f"(lo), "=f"(hi) : "l"(v));
    return lo + hi;
}

// jax.nn.gelu (approximate=True), tanh via exp (~1e-7 accurate)
__device__ __forceinline__ float gelu_t(float x) {
    float y = 0.7978845608028654f * (x + 0.044715f * x * x * x);
    float e = __expf(2.0f * y);
    float th = 1.0f - __fdividef(2.0f, e + 1.0f);
    return 0.5f * x * (1.0f + th);
}

// ---------------------------------------------------------------------------
__global__ void embed_kernel(const float* __restrict__ nodes,
                             const float* __restrict__ w,
                             const float* __restrict__ b, int Nv) {
    int idx = blockIdx.x * blockDim.x + threadIdx.x;
    if (idx >= Nv * 64) return;
    int n = idx >> 6, j = idx & 63;
    float a = b[j];
#pragma unroll
    for (int k = 0; k < 7; k++) a += nodes[n * 7 + k] * w[k * 64 + j];
    g_h[idx] = a;
}

__global__ void zero_recv_kernel(int n) {
    int i = blockIdx.x * blockDim.x + threadIdx.x;
    if (i < n) g_recv[i] = 0.0f;
}

// ---------------------------------------------------------------------------
// Fused edge MLP. CTA tile = 64 edges, 8 warps x 8 edges.
// Layer 1: lane owns j = lane+32u (4 j) for its warp's 8 edges; weight
// LDS.128 = 32 distinct j-rows (512B unique). Inputs distributed via shfl.
// hid aliases inb (inb dead after layer 1).
// ---------------------------------------------------------------------------
template <int DIN, bool HAS_E>
__global__ __launch_bounds__(256, 1) void edge_kernel(
    const int* __restrict__ senders, const int* __restrict__ receivers,
    const float* __restrict__ gvec,
    const float* __restrict__ w1, const float* __restrict__ b1,
    const float* __restrict__ w2, const float* __restrict__ b2,
    int En, int write_e) {
    constexpr int INP = DIN + 4;    // 212/148: INP/4 mod 8 == 5 (phase-clean)
    constexpr int W2P = 132;        // 33 qw: mod 8 == 1
    constexpr int HP = 132;
    constexpr int MB = 64;
    constexpr int NC = DIN / 4;

    extern __shared__ float sm[];
    float* w1t = sm;                    // 128*INP [j][k]
    float* w2t = w1t + 128 * INP;       // 64*W2P  [j][k] k<128
    float* b1s = w2t + 64 * W2P;        // 128
    float* b2s = b1s + 128;             // 64
    float* gs  = b2s + 64;              // 16
    int* sidx  = (int*)(gs + 16);       // 64
    int* ridx  = sidx + 64;             // 64
    float* inb = (float*)(ridx + 64);   // MB*INP  (aliased:)
    float* hid = inb;                   // MB*HP

    int tid = threadIdx.x;
    for (int i = tid; i < DIN * 128; i += 256) {
        int k = i >> 7, j = i & 127;
        w1t[j * INP + k] = w1[i];
    }
    for (int i = tid; i < 128 * 64; i += 256) {
        int k = i >> 6, j = i & 63;
        w2t[j * W2P + k] = w2[i];
    }
    if (tid < 128) b1s[tid] = b1[tid];
    else if (tid < 192) b2s[tid - 128] = b2[tid - 128];
    else if (tid < 208) gs[tid - 192] = gvec[tid - 192];
    __syncthreads();

    int w = tid >> 5, lane = tid & 31;
    int e8 = lane & 7;

    int nIter = (En + MB - 1) / MB;
    for (int it = blockIdx.x; it < nIter; it += gridDim.x) {
        int ebase = it * MB;
        // ---- A: indices ----
        if (tid < 64) {
            int e = ebase + tid; if (e >= En) e = En - 1;
            sidx[tid] = senders[e];
        } else if (tid < 128) {
            int e = ebase + tid - 64; if (e >= En) e = En - 1;
            ridx[tid - 64] = receivers[e];
        }
        __syncthreads();
        // ---- B: gather inputs ----
        {
            const float4* hp = (const float4*)g_h;
            const float4* gp4 = (const float4*)gs;
            for (int c = tid; c < MB * NC; c += 256) {
                int m = c / NC, q = c - m * NC;
                float4 v;
                if (HAS_E) {
                    int e = ebase + m; if (e >= En) e = En - 1;
                    if (q < 16)      v = ((const float4*)g_e)[(size_t)e * 16 + q];
                    else if (q < 32) v = hp[(size_t)sidx[m] * 16 + (q - 16)];
                    else if (q < 48) v = hp[(size_t)ridx[m] * 16 + (q - 32)];
                    else             v = gp4[q - 48];
                } else {
                    if (q < 16)      v = hp[(size_t)sidx[m] * 16 + q];
                    else if (q < 32) v = hp[(size_t)ridx[m] * 16 + (q - 16)];
                    else             v = gp4[q - 32];
                }
                ((float4*)(inb + m * INP))[q] = v;
            }
        }
        __syncthreads();
        // ---- C: layer 1 ----
        u64 acc[4][8];
#pragma unroll
        for (int u = 0; u < 4; u++)
#pragma unroll
            for (int e = 0; e < 8; e++) acc[u][e] = 0ull;
        {
            const float* inw = inb + (w * 8 + e8) * INP;
            const float* wb = w1t + lane * INP;
#pragma unroll 2
            for (int k4 = 0; k4 < DIN / 4; k4++) {
                float4 f = *(const float4*)(inw + 4 * k4);
                ulonglong2 wf[4];
#pragma unroll
                for (int u = 0; u < 4; u++)
                    wf[u] = *(const ulonglong2*)(wb + u * 32 * INP + 4 * k4);
#pragma unroll
                for (int e = 0; e < 8; e++) {
                    float ax = __shfl_sync(0xffffffffu, f.x, e);
                    float ay = __shfl_sync(0xffffffffu, f.y, e);
                    float az = __shfl_sync(0xffffffffu, f.z, e);
                    float aw = __shfl_sync(0xffffffffu, f.w, e);
                    u64 a01, a23;
                    PACK2(a01, ax, ay);
                    PACK2(a23, az, aw);
#pragma unroll
                    for (int u = 0; u < 4; u++) {
                        FMA2(acc[u][e], a01, wf[u].x);
                        FMA2(acc[u][e], a23, wf[u].y);
                    }
                }
            }
        }
        __syncthreads();   // all inb reads done before hid (alias) writes
        // ---- D: gelu + transposed store ----
#pragma unroll
        for (int e = 0; e < 8; e++)
#pragma unroll
            for (int u = 0; u < 4; u++) {
                int j = 32 * u + lane;
                hid[(w * 8 + e) * HP + j] = gelu_t(hadd2(acc[u][e]) + b1s[j]);
            }
        __syncthreads();
        // ---- E: layer 2 (lane owns j=lane, lane+32) ----
        u64 o0[8], o1[8];
#pragma unroll
        for (int e = 0; e < 8; e++) { o0[e] = 0ull; o1[e] = 0ull; }
        {
            const float* hw = hid + (w * 8 + e8) * HP;
            const float* wa = w2t + lane * W2P;
            const float* wbp = w2t + (lane + 32) * W2P;
#pragma unroll 2
            for (int k4 = 0; k4 < 32; k4++) {
                float4 f = *(const float4*)(hw + 4 * k4);
                ulonglong2 va = *(const ulonglong2*)(wa + 4 * k4);
                ulonglong2 vb = *(const ulonglong2*)(wbp + 4 * k4);
#pragma unroll
                for (int e = 0; e < 8; e++) {
                    float ax = __shfl_sync(0xffffffffu, f.x, e);
                    float ay = __shfl_sync(0xffffffffu, f.y, e);
                    float az = __shfl_sync(0xffffffffu, f.z, e);
                    float aw = __shfl_sync(0xffffffffu, f.w, e);
                    u64 a01, a23;
                    PACK2(a01, ax, ay);
                    PACK2(a23, az, aw);
                    FMA2(o0[e], a01, va.x);
                    FMA2(o0[e], a23, va.y);
                    FMA2(o1[e], a01, vb.x);
                    FMA2(o1[e], a23, vb.y);
                }
            }
        }
        // ---- F: scatter ----
#pragma unroll
        for (int e = 0; e < 8; e++) {
            int eid = ebase + w * 8 + e;
            if (eid < En) {
                int rc = ridx[w * 8 + e];
                float u0 = hadd2(o0[e]) + b2s[lane];
                float u1 = hadd2(o1[e]) + b2s[lane + 32];
                if (write_e) {
                    g_e[(size_t)eid * 64 + lane] = u0;
                    g_e[(size_t)eid * 64 + 32 + lane] = u1;
                }
                atomicAdd(&g_recv[(size_t)rc * 64 + lane], u0);
                atomicAdd(&g_recv[(size_t)rc * 64 + 32 + lane], u1);
            }
        }
        __syncthreads();   // hid/ridx reads done before next iter overwrites
    }
}

// ---------------------------------------------------------------------------
// Fused node MLP + residual + LayerNorm. Same structure, DIN=144.
// ---------------------------------------------------------------------------
__global__ __launch_bounds__(256, 1) void node_kernel(
    const float* __restrict__ gvec,
    const float* __restrict__ w1, const float* __restrict__ b1,
    const float* __restrict__ w2, const float* __restrict__ b2,
    const float* __restrict__ lnsc, const float* __restrict__ lnbi, int Nv) {
    constexpr int DIN = 144, INP = 148, W2P = 132, HP = 132, MB = 64, NC = 36;
    extern __shared__ float sm[];
    float* w1t = sm;
    float* w2t = w1t + 128 * INP;
    float* b1s = w2t + 64 * W2P;
    float* b2s = b1s + 128;
    float* gs  = b2s + 64;
    float* lns = gs + 16;
    float* lnb = lns + 64;
    float* inb = lnb + 64;
    float* hid = inb;                  // alias

    int tid = threadIdx.x;
    for (int i = tid; i < DIN * 128; i += 256) {
        int k = i >> 7, j = i & 127;
        w1t[j * INP + k] = w1[i];
    }
    for (int i = tid; i < 128 * 64; i += 256) {
        int k = i >> 6, j = i & 63;
        w2t[j * W2P + k] = w2[i];
    }
    if (tid < 128) b1s[tid] = b1[tid];
    else if (tid < 192) b2s[tid - 128] = b2[tid - 128];
    else if (tid < 208) gs[tid - 192] = gvec[tid - 192];
    for (int i = tid; i < 64; i += 256) { lns[i] = lnsc[i]; lnb[i] = lnbi[i]; }
    __syncthreads();

    int w = tid >> 5, lane = tid & 31;
    int e8 = lane & 7;

    int nIter = (Nv + MB - 1) / MB;
    for (int it = blockIdx.x; it < nIter; it += gridDim.x) {
        int nbase = it * MB;
        // ---- gather ----
        {
            const float4* hp = (const float4*)g_h;
            const float4* rp = (const float4*)g_recv;
            const float4* gp4 = (const float4*)gs;
            for (int c = tid; c < MB * NC; c += 256) {
                int m = c / NC, q = c - m * NC;
                int nid = nbase + m; if (nid >= Nv) nid = Nv - 1;
                float4 v;
                if (q < 16)      v = hp[(size_t)nid * 16 + q];
                else if (q < 32) v = rp[(size_t)nid * 16 + (q - 16)];
                else             v = gp4[q - 32];
                ((float4*)(inb + m * INP))[q] = v;
            }
        }
        __syncthreads();
        // ---- layer 1 ----
        u64 acc[4][8];
#pragma unroll
        for (int u = 0; u < 4; u++)
#pragma unroll
            for (int e = 0; e < 8; e++) acc[u][e] = 0ull;
        {
            const float* inw = inb + (w * 8 + e8) * INP;
            const float* wb = w1t + lane * INP;
#pragma unroll 2
            for (int k4 = 0; k4 < DIN / 4; k4++) {
                float4 f = *(const float4*)(inw + 4 * k4);
                ulonglong2 wf[4];
#pragma unroll
                for (int u = 0; u < 4; u++)
                    wf[u] = *(const ulonglong2*)(wb + u * 32 * INP + 4 * k4);
#pragma unroll
                for (int e = 0; e < 8; e++) {
                    float ax = __shfl_sync(0xffffffffu, f.x, e);
                    float ay = __shfl_sync(0xffffffffu, f.y, e);
                    float az = __shfl_sync(0xffffffffu, f.z, e);
                    float aw = __shfl_sync(0xffffffffu, f.w, e);
                    u64 a01, a23;
                    PACK2(a01, ax, ay);
                    PACK2(a23, az, aw);
#pragma unroll
                    for (int u = 0; u < 4; u++) {
                        FMA2(acc[u][e], a01, wf[u].x);
                        FMA2(acc[u][e], a23, wf[u].y);
                    }
                }
            }
        }
        __syncthreads();
        // ---- gelu + transposed store ----
#pragma unroll
        for (int e = 0; e < 8; e++)
#pragma unroll
            for (int u = 0; u < 4; u++) {
                int j = 32 * u + lane;
                hid[(w * 8 + e) * HP + j] = gelu_t(hadd2(acc[u][e]) + b1s[j]);
            }
        __syncthreads();
        // ---- layer 2 ----
        u64 o0[8], o1[8];
#pragma unroll
        for (int e = 0; e < 8; e++) { o0[e] = 0ull; o1[e] = 0ull; }
        {
            const float* hw = hid + (w * 8 + e8) * HP;
            const float* wa = w2t + lane * W2P;
            const float* wbp = w2t + (lane + 32) * W2P;
#pragma unroll 2
            for (int k4 = 0; k4 < 32; k4++) {
                float4 f = *(const float4*)(hw + 4 * k4);
                ulonglong2 va = *(const ulonglong2*)(wa + 4 * k4);
                ulonglong2 vb = *(const ulonglong2*)(wbp + 4 * k4);
#pragma unroll
                for (int e = 0; e < 8; e++) {
                    float ax = __shfl_sync(0xffffffffu, f.x, e);
                    float ay = __shfl_sync(0xffffffffu, f.y, e);
                    float az = __shfl_sync(0xffffffffu, f.z, e);
                    float aw = __shfl_sync(0xffffffffu, f.w, e);
                    u64 a01, a23;
                    PACK2(a01, ax, ay);
                    PACK2(a23, az, aw);
                    FMA2(o0[e], a01, va.x);
                    FMA2(o0[e], a23, va.y);
                    FMA2(o1[e], a01, vb.x);
                    FMA2(o1[e], a23, vb.y);
                }
            }
        }
        // ---- residual + LayerNorm (h re-read from global; L1/L2 hit) ----
#pragma unroll
        for (int e = 0; e < 8; e++) {
            int nid = nbase + w * 8 + e;
            int nc = nid < Nv ? nid : Nv - 1;
            float h0 = g_h[(size_t)nc * 64 + lane];
            float h1 = g_h[(size_t)nc * 64 + 32 + lane];
            float x0 = h0 + hadd2(o0[e]) + b2s[lane];
            float x1 = h1 + hadd2(o1[e]) + b2s[lane + 32];
            float s = x0 + x1, q = x0 * x0 + x1 * x1;
#pragma unroll
            for (int d = 16; d; d >>= 1) {
                s += __shfl_xor_sync(0xffffffffu, s, d);
                q += __shfl_xor_sync(0xffffffffu, q, d);
            }
            float mu = s * (1.0f / 64.0f);
            float var = q * (1.0f / 64.0f) - mu * mu;
            float inv = rsqrtf(var + 1e-6f);
            if (nid < Nv) {
                g_h[(size_t)nid * 64 + lane]      = (x0 - mu) * inv * lns[lane] + lnb[lane];
                g_h[(size_t)nid * 64 + 32 + lane] = (x1 - mu) * inv * lns[lane + 32] + lnb[lane + 32];
            }
        }
        __syncthreads();   // hid reads done before next gather (alias)
    }
}

// ---------------------------------------------------------------------------
__global__ void decode_kernel(const float* __restrict__ dec_w,
                              const float* __restrict__ dec_b,
                              float* __restrict__ out, int Nv) {
    int gwarp = (blockIdx.x * blockDim.x + threadIdx.x) >> 5;
    int lane = threadIdx.x & 31;
    int nWarps = (gridDim.x * blockDim.x) >> 5;
    for (int n = gwarp; n < Nv; n += nWarps) {
        float h0 = g_h[n * 64 + lane];
        float h1 = g_h[n * 64 + 32 + lane];
        float p[7];
#pragma unroll
        for (int k = 0; k < 7; k++)
            p[k] = h0 * dec_w[lane * 7 + k] + h1 * dec_w[(lane + 32) * 7 + k];
#pragma unroll
        for (int k = 0; k < 7; k++)
#pragma unroll
            for (int d = 16; d; d >>= 1) p[k] += __shfl_xor_sync(0xffffffffu, p[k], d);
        if (lane < 7) out[n * 7 + lane] = p[lane] + dec_b[lane];
    }
}

// ---------------------------------------------------------------------------
extern "C" void kernel_launch(void* const* d_in, const int* in_sizes, int n_in,
                              void* d_out, int out_size) {
    const float* nodes   = (const float*)d_in[0];
    const int*   senders = (const int*)d_in[1];
    const int*   recvrs  = (const int*)d_in[2];
    const float* g       = (const float*)d_in[3];
    const float* embed_w = (const float*)d_in[4];
    const float* embed_b = (const float*)d_in[5];
    const float* ew1f    = (const float*)d_in[6];
    const float* ew1r    = (const float*)d_in[7];
    const float* eb1     = (const float*)d_in[8];
    const float* ew2     = (const float*)d_in[9];
    const float* eb2     = (const float*)d_in[10];
    const float* nw1     = (const float*)d_in[11];
    const float* nb1     = (const float*)d_in[12];
    const float* nw2     = (const float*)d_in[13];
    const float* nb2     = (const float*)d_in[14];
    const float* lnsc    = (const float*)d_in[15];
    const float* lnbi    = (const float*)d_in[16];
    const float* dec_w   = (const float*)d_in[17];
    const float* dec_b   = (const float*)d_in[18];
    float* out = (float*)d_out;

    int En = in_sizes[1];
    int Nv = in_sizes[0] / 7;

    // exact smem sizes (floats): weights + biases + g + idx(128 words) + inb
    size_t sm_e0 = (size_t)(128 * 148 + 64 * 132 + 128 + 64 + 16 + 128 + 64 * 148) * 4;
    size_t sm_e1 = (size_t)(128 * 212 + 64 * 132 + 128 + 64 + 16 + 128 + 64 * 212) * 4;
    size_t sm_n  = (size_t)(128 * 148 + 64 * 132 + 128 + 64 + 16 + 64 + 64 + 64 * 148) * 4;

    cudaFuncSetAttribute(edge_kernel<144, false>,
                         cudaFuncAttributeMaxDynamicSharedMemorySize, (int)sm_e0);
    cudaFuncSetAttribute(edge_kernel<208, true>,
                         cudaFuncAttributeMaxDynamicSharedMemorySize, (int)sm_e1);
    cudaFuncSetAttribute(node_kernel,
                         cudaFuncAttributeMaxDynamicSharedMemorySize, (int)sm_n);

    const int GRID = 148;

    embed_kernel<<<(Nv * 64 + 255) / 256, 256>>>(nodes, embed_w, embed_b, Nv);

    for (int t = 0; t < 3; t++) {
        zero_recv_kernel<<<(Nv * 64 + 255) / 256, 256>>>(Nv * 64);
        if (t == 0) {
            edge_kernel<144, false><<<GRID, 256, sm_e0>>>(
                senders, recvrs, g, ew1f, eb1, ew2, eb2, En, 1);
        } else {
            edge_kernel<208, true><<<GRID, 256, sm_e1>>>(
                senders, recvrs, g,
                ew1r + (size_t)(t - 1) * 208 * 128,
                eb1 + t * 128, ew2 + (size_t)t * 128 * 64, eb2 + t * 64,
                En, (t == 2) ? 0 : 1);
        }
        node_kernel<<<GRID, 256, sm_n>>>(
            g, nw1 + (size_t)t * 144 * 128, nb1 + t * 128,
            nw2 + (size_t)t * 128 * 64, nb2 + t * 64,
            lnsc + t * 64, lnbi + t * 64, Nv);
    }

    decode_kernel<<<208, 256>>>(dec_w, dec_b, out, Nv);
}

// round 6
// speedup vs baseline: 1.4599x; 1.2725x over previous
#include <cuda_runtime.h>
#include <math.h>

#define NN 50000
#define EE 800000

__device__ float g_h[NN * 64];
__device__ float g_e[EE * 64];
__device__ float g_recv[NN * 64];

typedef unsigned long long u64;

#define FMA2(d, a, b) asm("fma.rn.f32x2 %0, %1, %2, %0;" : "+l"(d) : "l"(a), "l"(b))

__device__ __forceinline__ float hadd2(u64 v) {
    float lo, hi;
    asm("mov.b64 {%0, %1}, %2;" : "=f"(lo), "=f"(hi) : "l"(v));
    return lo + hi;
}

// jax.nn.gelu (approximate=True), tanh via exp (~1e-7 accurate)
__device__ __forceinline__ float gelu_t(float x) {
    float y = 0.7978845608028654f * (x + 0.044715f * x * x * x);
    float e = __expf(2.0f * y);
    float th = 1.0f - __fdividef(2.0f, e + 1.0f);
    return 0.5f * x * (1.0f + th);
}

// ---------------------------------------------------------------------------
__global__ void embed_kernel(const float* __restrict__ nodes,
                             const float* __restrict__ w,
                             const float* __restrict__ b, int Nv) {
    int idx = blockIdx.x * blockDim.x + threadIdx.x;
    if (idx >= Nv * 64) return;
    int n = idx >> 6, j = idx & 63;
    float a = b[j];
#pragma unroll
    for (int k = 0; k < 7; k++) a += nodes[n * 7 + k] * w[k * 64 + j];
    g_h[idx] = a;
}

__global__ void zero_recv_kernel(int n) {
    int i = blockIdx.x * blockDim.x + threadIdx.x;
    if (i < n) g_recv[i] = 0.0f;
}

// ---------------------------------------------------------------------------
// Fused edge MLP. CTA tile = 64 edges, warp = 8 edges x 128 j.
// Weights: LDS.128, 32 distinct rows (conflict-free via stride pad).
// Inputs: warp-uniform LDS.128 = HW broadcast (1 wavefront), lands as 2xu64.
// hid aliases inb (dead after layer 1).
// ---------------------------------------------------------------------------
template <int DIN, bool HAS_E>
__global__ __launch_bounds__(256, 1) void edge_kernel(
    const int* __restrict__ senders, const int* __restrict__ receivers,
    const float* __restrict__ gvec,
    const float* __restrict__ w1, const float* __restrict__ b1,
    const float* __restrict__ w2, const float* __restrict__ b2,
    int En, int write_e) {
    constexpr int INP = DIN + 4;    // 212/148: lane*INP*4 mod 128 spans 16B slots
    constexpr int W2P = 132;
    constexpr int HP = 132;
    constexpr int MB = 64;
    constexpr int NC = DIN / 4;

    extern __shared__ float sm[];
    float* w1t = sm;                    // 128*INP [j][k]
    float* w2t = w1t + 128 * INP;       // 64*W2P  [j][k] k<128
    float* b1s = w2t + 64 * W2P;        // 128
    float* b2s = b1s + 128;             // 64
    float* gs  = b2s + 64;              // 16
    int* sidx  = (int*)(gs + 16);       // 64
    int* ridx  = sidx + 64;             // 64
    float* inb = (float*)(ridx + 64);   // MB*INP  (16B-aligned)
    float* hid = inb;                   // alias: MB*HP

    int tid = threadIdx.x;
    for (int i = tid; i < DIN * 128; i += 256) {
        int k = i >> 7, j = i & 127;
        w1t[j * INP + k] = w1[i];
    }
    for (int i = tid; i < 128 * 64; i += 256) {
        int k = i >> 6, j = i & 63;
        w2t[j * W2P + k] = w2[i];
    }
    if (tid < 128) b1s[tid] = b1[tid];
    else if (tid < 192) b2s[tid - 128] = b2[tid - 128];
    else if (tid < 208) gs[tid - 192] = gvec[tid - 192];
    __syncthreads();

    int w = tid >> 5, lane = tid & 31;

    int nIter = (En + MB - 1) / MB;
    for (int it = blockIdx.x; it < nIter; it += gridDim.x) {
        int ebase = it * MB;
        // ---- A: indices ----
        if (tid < 64) {
            int e = ebase + tid; if (e >= En) e = En - 1;
            sidx[tid] = senders[e];
        } else if (tid < 128) {
            int e = ebase + tid - 64; if (e >= En) e = En - 1;
            ridx[tid - 64] = receivers[e];
        }
        __syncthreads();
        // ---- B: gather inputs ----
        {
            const float4* hp = (const float4*)g_h;
            const float4* gp4 = (const float4*)gs;
            for (int c = tid; c < MB * NC; c += 256) {
                int m = c / NC, q = c - m * NC;
                float4 v;
                if (HAS_E) {
                    int e = ebase + m; if (e >= En) e = En - 1;
                    if (q < 16)      v = ((const float4*)g_e)[(size_t)e * 16 + q];
                    else if (q < 32) v = hp[(size_t)sidx[m] * 16 + (q - 16)];
                    else if (q < 48) v = hp[(size_t)ridx[m] * 16 + (q - 32)];
                    else             v = gp4[q - 48];
                } else {
                    if (q < 16)      v = hp[(size_t)sidx[m] * 16 + q];
                    else if (q < 32) v = hp[(size_t)ridx[m] * 16 + (q - 16)];
                    else             v = gp4[q - 32];
                }
                ((float4*)(inb + m * INP))[q] = v;
            }
        }
        __syncthreads();
        // ---- C: layer 1 ----
        u64 acc[4][8];
#pragma unroll
        for (int u = 0; u < 4; u++)
#pragma unroll
            for (int e = 0; e < 8; e++) acc[u][e] = 0ull;
        {
            const float* inw = inb + (w * 8) * INP;     // warp-uniform
            const float* wb = w1t + lane * INP;
#pragma unroll 2
            for (int k4 = 0; k4 < DIN / 4; k4++) {
                ulonglong2 wf[4];
#pragma unroll
                for (int u = 0; u < 4; u++)
                    wf[u] = *(const ulonglong2*)(wb + u * 32 * INP + 4 * k4);
#pragma unroll
                for (int e = 0; e < 8; e++) {
                    ulonglong2 av = *(const ulonglong2*)(inw + e * INP + 4 * k4);
#pragma unroll
                    for (int u = 0; u < 4; u++) {
                        FMA2(acc[u][e], av.x, wf[u].x);
                        FMA2(acc[u][e], av.y, wf[u].y);
                    }
                }
            }
        }
        __syncthreads();   // all inb reads done before hid (alias) writes
        // ---- D: gelu + transposed store ----
#pragma unroll
        for (int e = 0; e < 8; e++)
#pragma unroll
            for (int u = 0; u < 4; u++) {
                int j = 32 * u + lane;
                hid[(w * 8 + e) * HP + j] = gelu_t(hadd2(acc[u][e]) + b1s[j]);
            }
        __syncthreads();
        // ---- E: layer 2 (lane owns j = lane, lane+32) ----
        u64 o0[8], o1[8];
#pragma unroll
        for (int e = 0; e < 8; e++) { o0[e] = 0ull; o1[e] = 0ull; }
        {
            const float* hw = hid + (w * 8) * HP;       // warp-uniform
            const float* wa = w2t + lane * W2P;
            const float* wbp = w2t + (lane + 32) * W2P;
#pragma unroll 2
            for (int k4 = 0; k4 < 32; k4++) {
                ulonglong2 va = *(const ulonglong2*)(wa + 4 * k4);
                ulonglong2 vb = *(const ulonglong2*)(wbp + 4 * k4);
#pragma unroll
                for (int e = 0; e < 8; e++) {
                    ulonglong2 av = *(const ulonglong2*)(hw + e * HP + 4 * k4);
                    FMA2(o0[e], av.x, va.x);
                    FMA2(o0[e], av.y, va.y);
                    FMA2(o1[e], av.x, vb.x);
                    FMA2(o1[e], av.y, vb.y);
                }
            }
        }
        // ---- F: scatter ----
#pragma unroll
        for (int e = 0; e < 8; e++) {
            int eid = ebase + w * 8 + e;
            if (eid < En) {
                int rc = ridx[w * 8 + e];
                float u0 = hadd2(o0[e]) + b2s[lane];
                float u1 = hadd2(o1[e]) + b2s[lane + 32];
                if (write_e) {
                    g_e[(size_t)eid * 64 + lane] = u0;
                    g_e[(size_t)eid * 64 + 32 + lane] = u1;
                }
                atomicAdd(&g_recv[(size_t)rc * 64 + lane], u0);
                atomicAdd(&g_recv[(size_t)rc * 64 + 32 + lane], u1);
            }
        }
        __syncthreads();   // hid/ridx reads done before next iter overwrites
    }
}

// ---------------------------------------------------------------------------
// Fused node MLP + residual + LayerNorm. Same structure, DIN=144.
// ---------------------------------------------------------------------------
__global__ __launch_bounds__(256, 1) void node_kernel(
    const float* __restrict__ gvec,
    const float* __restrict__ w1, const float* __restrict__ b1,
    const float* __restrict__ w2, const float* __restrict__ b2,
    const float* __restrict__ lnsc, const float* __restrict__ lnbi, int Nv) {
    constexpr int DIN = 144, INP = 148, W2P = 132, HP = 132, MB = 64, NC = 36;
    extern __shared__ float sm[];
    float* w1t = sm;
    float* w2t = w1t + 128 * INP;
    float* b1s = w2t + 64 * W2P;
    float* b2s = b1s + 128;
    float* gs  = b2s + 64;
    float* lns = gs + 16;
    float* lnb = lns + 64;
    float* inb = lnb + 64;
    float* hid = inb;                  // alias

    int tid = threadIdx.x;
    for (int i = tid; i < DIN * 128; i += 256) {
        int k = i >> 7, j = i & 127;
        w1t[j * INP + k] = w1[i];
    }
    for (int i = tid; i < 128 * 64; i += 256) {
        int k = i >> 6, j = i & 63;
        w2t[j * W2P + k] = w2[i];
    }
    if (tid < 128) b1s[tid] = b1[tid];
    else if (tid < 192) b2s[tid - 128] = b2[tid - 128];
    else if (tid < 208) gs[tid - 192] = gvec[tid - 192];
    for (int i = tid; i < 64; i += 256) { lns[i] = lnsc[i]; lnb[i] = lnbi[i]; }
    __syncthreads();

    int w = tid >> 5, lane = tid & 31;

    int nIter = (Nv + MB - 1) / MB;
    for (int it = blockIdx.x; it < nIter; it += gridDim.x) {
        int nbase = it * MB;
        // ---- gather ----
        {
            const float4* hp = (const float4*)g_h;
            const float4* rp = (const float4*)g_recv;
            const float4* gp4 = (const float4*)gs;
            for (int c = tid; c < MB * NC; c += 256) {
                int m = c / NC, q = c - m * NC;
                int nid = nbase + m; if (nid >= Nv) nid = Nv - 1;
                float4 v;
                if (q < 16)      v = hp[(size_t)nid * 16 + q];
                else if (q < 32) v = rp[(size_t)nid * 16 + (q - 16)];
                else             v = gp4[q - 32];
                ((float4*)(inb + m * INP))[q] = v;
            }
        }
        __syncthreads();
        // ---- layer 1 ----
        u64 acc[4][8];
#pragma unroll
        for (int u = 0; u < 4; u++)
#pragma unroll
            for (int e = 0; e < 8; e++) acc[u][e] = 0ull;
        {
            const float* inw = inb + (w * 8) * INP;
            const float* wb = w1t + lane * INP;
#pragma unroll 2
            for (int k4 = 0; k4 < DIN / 4; k4++) {
                ulonglong2 wf[4];
#pragma unroll
                for (int u = 0; u < 4; u++)
                    wf[u] = *(const ulonglong2*)(wb + u * 32 * INP + 4 * k4);
#pragma unroll
                for (int e = 0; e < 8; e++) {
                    ulonglong2 av = *(const ulonglong2*)(inw + e * INP + 4 * k4);
#pragma unroll
                    for (int u = 0; u < 4; u++) {
                        FMA2(acc[u][e], av.x, wf[u].x);
                        FMA2(acc[u][e], av.y, wf[u].y);
                    }
                }
            }
        }
        __syncthreads();
        // ---- gelu + transposed store ----
#pragma unroll
        for (int e = 0; e < 8; e++)
#pragma unroll
            for (int u = 0; u < 4; u++) {
                int j = 32 * u + lane;
                hid[(w * 8 + e) * HP + j] = gelu_t(hadd2(acc[u][e]) + b1s[j]);
            }
        __syncthreads();
        // ---- layer 2 ----
        u64 o0[8], o1[8];
#pragma unroll
        for (int e = 0; e < 8; e++) { o0[e] = 0ull; o1[e] = 0ull; }
        {
            const float* hw = hid + (w * 8) * HP;
            const float* wa = w2t + lane * W2P;
            const float* wbp = w2t + (lane + 32) * W2P;
#pragma unroll 2
            for (int k4 = 0; k4 < 32; k4++) {
                ulonglong2 va = *(const ulonglong2*)(wa + 4 * k4);
                ulonglong2 vb = *(const ulonglong2*)(wbp + 4 * k4);
#pragma unroll
                for (int e = 0; e < 8; e++) {
                    ulonglong2 av = *(const ulonglong2*)(hw + e * HP + 4 * k4);
                    FMA2(o0[e], av.x, va.x);
                    FMA2(o0[e], av.y, va.y);
                    FMA2(o1[e], av.x, vb.x);
                    FMA2(o1[e], av.y, vb.y);
                }
            }
        }
        // ---- residual + LayerNorm ----
#pragma unroll
        for (int e = 0; e < 8; e++) {
            int nid = nbase + w * 8 + e;
            int nc = nid < Nv ? nid : Nv - 1;
            float h0 = g_h[(size_t)nc * 64 + lane];
            float h1 = g_h[(size_t)nc * 64 + 32 + lane];
            float x0 = h0 + hadd2(o0[e]) + b2s[lane];
            float x1 = h1 + hadd2(o1[e]) + b2s[lane + 32];
            float s = x0 + x1, q = x0 * x0 + x1 * x1;
#pragma unroll
            for (int d = 16; d; d >>= 1) {
                s += __shfl_xor_sync(0xffffffffu, s, d);
                q += __shfl_xor_sync(0xffffffffu, q, d);
            }
            float mu = s * (1.0f / 64.0f);
            float var = q * (1.0f / 64.0f) - mu * mu;
            float inv = rsqrtf(var + 1e-6f);
            if (nid < Nv) {
                g_h[(size_t)nid * 64 + lane]      = (x0 - mu) * inv * lns[lane] + lnb[lane];
                g_h[(size_t)nid * 64 + 32 + lane] = (x1 - mu) * inv * lns[lane + 32] + lnb[lane + 32];
            }
        }
        __syncthreads();
    }
}

// ---------------------------------------------------------------------------
__global__ void decode_kernel(const float* __restrict__ dec_w,
                              const float* __restrict__ dec_b,
                              float* __restrict__ out, int Nv) {
    int gwarp = (blockIdx.x * blockDim.x + threadIdx.x) >> 5;
    int lane = threadIdx.x & 31;
    int nWarps = (gridDim.x * blockDim.x) >> 5;
    for (int n = gwarp; n < Nv; n += nWarps) {
        float h0 = g_h[n * 64 + lane];
        float h1 = g_h[n * 64 + 32 + lane];
        float p[7];
#pragma unroll
        for (int k = 0; k < 7; k++)
            p[k] = h0 * dec_w[lane * 7 + k] + h1 * dec_w[(lane + 32) * 7 + k];
#pragma unroll
        for (int k = 0; k < 7; k++)
#pragma unroll
            for (int d = 16; d; d >>= 1) p[k] += __shfl_xor_sync(0xffffffffu, p[k], d);
        if (lane < 7) out[n * 7 + lane] = p[lane] + dec_b[lane];
    }
}

// ---------------------------------------------------------------------------
extern "C" void kernel_launch(void* const* d_in, const int* in_sizes, int n_in,
                              void* d_out, int out_size) {
    const float* nodes   = (const float*)d_in[0];
    const int*   senders = (const int*)d_in[1];
    const int*   recvrs  = (const int*)d_in[2];
    const float* g       = (const float*)d_in[3];
    const float* embed_w = (const float*)d_in[4];
    const float* embed_b = (const float*)d_in[5];
    const float* ew1f    = (const float*)d_in[6];
    const float* ew1r    = (const float*)d_in[7];
    const float* eb1     = (const float*)d_in[8];
    const float* ew2     = (const float*)d_in[9];
    const float* eb2     = (const float*)d_in[10];
    const float* nw1     = (const float*)d_in[11];
    const float* nb1     = (const float*)d_in[12];
    const float* nw2     = (const float*)d_in[13];
    const float* nb2     = (const float*)d_in[14];
    const float* lnsc    = (const float*)d_in[15];
    const float* lnbi    = (const float*)d_in[16];
    const float* dec_w   = (const float*)d_in[17];
    const float* dec_b   = (const float*)d_in[18];
    float* out = (float*)d_out;

    int En = in_sizes[1];
    int Nv = in_sizes[0] / 7;

    size_t sm_e0 = (size_t)(128 * 148 + 64 * 132 + 128 + 64 + 16 + 128 + 64 * 148) * 4;
    size_t sm_e1 = (size_t)(128 * 212 + 64 * 132 + 128 + 64 + 16 + 128 + 64 * 212) * 4;
    size_t sm_n  = (size_t)(128 * 148 + 64 * 132 + 128 + 64 + 16 + 64 + 64 + 64 * 148) * 4;

    cudaFuncSetAttribute(edge_kernel<144, false>,
                         cudaFuncAttributeMaxDynamicSharedMemorySize, (int)sm_e0);
    cudaFuncSetAttribute(edge_kernel<208, true>,
                         cudaFuncAttributeMaxDynamicSharedMemorySize, (int)sm_e1);
    cudaFuncSetAttribute(node_kernel,
                         cudaFuncAttributeMaxDynamicSharedMemorySize, (int)sm_n);

    const int GRID = 148;

    embed_kernel<<<(Nv * 64 + 255) / 256, 256>>>(nodes, embed_w, embed_b, Nv);

    for (int t = 0; t < 3; t++) {
        zero_recv_kernel<<<(Nv * 64 + 255) / 256, 256>>>(Nv * 64);
        if (t == 0) {
            edge_kernel<144, false><<<GRID, 256, sm_e0>>>(
                senders, recvrs, g, ew1f, eb1, ew2, eb2, En, 1);
        } else {
            edge_kernel<208, true><<<GRID, 256, sm_e1>>>(
                senders, recvrs, g,
                ew1r + (size_t)(t - 1) * 208 * 128,
                eb1 + t * 128, ew2 + (size_t)t * 128 * 64, eb2 + t * 64,
                En, (t == 2) ? 0 : 1);
        }
        node_kernel<<<GRID, 256, sm_n>>>(
            g, nw1 + (size_t)t * 144 * 128, nb1 + t * 128,
            nw2 + (size_t)t * 128 * 64, nb2 + t * 64,
            lnsc + t * 64, lnbi + t * 64, Nv);
    }

    decode_kernel<<<208, 256>>>(dec_w, dec_b, out, Nv);
}

// round 7
// speedup vs baseline: 1.6778x; 1.1492x over previous
#include <cuda_runtime.h>
#include <math.h>

#define NN 50000
#define EE 800000

__device__ float g_h[NN * 64];
__device__ float g_e[EE * 64];
__device__ float g_recv[NN * 64];

typedef unsigned long long u64;

#define FMA2(d, a, b) asm("fma.rn.f32x2 %0, %1, %2, %0;" : "+l"(d) : "l"(a), "l"(b))

__device__ __forceinline__ float hadd2(u64 v) {
    float lo, hi;
    asm("mov.b64 {%0, %1}, %2;" : "=f"(lo), "=f"(hi) : "l"(v));
    return lo + hi;
}

// jax.nn.gelu (approximate=True), tanh via exp (~1e-7 accurate)
__device__ __forceinline__ float gelu_t(float x) {
    float y = 0.7978845608028654f * (x + 0.044715f * x * x * x);
    float e = __expf(2.0f * y);
    float th = 1.0f - __fdividef(2.0f, e + 1.0f);
    return 0.5f * x * (1.0f + th);
}

// ---------------------------------------------------------------------------
__global__ void embed_kernel(const float* __restrict__ nodes,
                             const float* __restrict__ w,
                             const float* __restrict__ b, int Nv) {
    int idx = blockIdx.x * blockDim.x + threadIdx.x;
    if (idx >= Nv * 64) return;
    int n = idx >> 6, j = idx & 63;
    float a = b[j];
#pragma unroll
    for (int k = 0; k < 7; k++) a += nodes[n * 7 + k] * w[k * 64 + j];
    g_h[idx] = a;
}

__global__ void zero_recv_kernel(int n) {
    int i = blockIdx.x * blockDim.x + threadIdx.x;
    if (i < n) g_recv[i] = 0.0f;
}

// ---------------------------------------------------------------------------
// Fused edge MLP. 384 threads = 12 warps; CTA tile = 96 edges (8/warp).
// Weights: LDS.128, 32 distinct rows/phase (stride pad -> conflict-free).
// Inputs: warp-uniform LDS.128 broadcast. hid aliases inb.
// ---------------------------------------------------------------------------
template <int DIN, bool HAS_E>
__global__ __launch_bounds__(384, 1) void edge_kernel(
    const int* __restrict__ senders, const int* __restrict__ receivers,
    const float* __restrict__ gvec,
    const float* __restrict__ w1, const float* __restrict__ b1,
    const float* __restrict__ w2, const float* __restrict__ b2,
    int En, int write_e) {
    constexpr int INP = DIN + 4;
    constexpr int W2P = 132;
    constexpr int HP = 132;
    constexpr int MB = 96;
    constexpr int NT = 384;
    constexpr int NC = DIN / 4;

    extern __shared__ float sm[];
    float* w1t = sm;                    // 128*INP [j][k]
    float* w2t = w1t + 128 * INP;       // 64*W2P  [j][k] k<128
    float* b1s = w2t + 64 * W2P;        // 128
    float* b2s = b1s + 128;             // 64
    float* gs  = b2s + 64;              // 16
    int* sidx  = (int*)(gs + 16);       // 96
    int* ridx  = sidx + MB;             // 96
    float* inb = (float*)(ridx + MB);   // MB*INP (16B-aligned)
    float* hid = inb;                   // alias: MB*HP

    int tid = threadIdx.x;
    for (int i = tid; i < DIN * 128; i += NT) {
        int k = i >> 7, j = i & 127;
        w1t[j * INP + k] = w1[i];
    }
    for (int i = tid; i < 128 * 64; i += NT) {
        int k = i >> 6, j = i & 63;
        w2t[j * W2P + k] = w2[i];
    }
    if (tid < 128) b1s[tid] = b1[tid];
    else if (tid < 192) b2s[tid - 128] = b2[tid - 128];
    else if (tid < 208) gs[tid - 192] = gvec[tid - 192];
    __syncthreads();

    int w = tid >> 5, lane = tid & 31;

    int nIter = (En + MB - 1) / MB;
    for (int it = blockIdx.x; it < nIter; it += gridDim.x) {
        int ebase = it * MB;
        // ---- A: indices ----
        if (tid < MB) {
            int e = ebase + tid; if (e >= En) e = En - 1;
            sidx[tid] = senders[e];
        } else if (tid < 2 * MB) {
            int e = ebase + tid - MB; if (e >= En) e = En - 1;
            ridx[tid - MB] = receivers[e];
        }
        __syncthreads();
        // ---- B: gather inputs ----
        {
            const float4* hp = (const float4*)g_h;
            const float4* gp4 = (const float4*)gs;
            for (int c = tid; c < MB * NC; c += NT) {
                int m = c / NC, q = c - m * NC;
                float4 v;
                if (HAS_E) {
                    int e = ebase + m; if (e >= En) e = En - 1;
                    if (q < 16)      v = ((const float4*)g_e)[(size_t)e * 16 + q];
                    else if (q < 32) v = hp[(size_t)sidx[m] * 16 + (q - 16)];
                    else if (q < 48) v = hp[(size_t)ridx[m] * 16 + (q - 32)];
                    else             v = gp4[q - 48];
                } else {
                    if (q < 16)      v = hp[(size_t)sidx[m] * 16 + q];
                    else if (q < 32) v = hp[(size_t)ridx[m] * 16 + (q - 16)];
                    else             v = gp4[q - 32];
                }
                ((float4*)(inb + m * INP))[q] = v;
            }
        }
        __syncthreads();
        // ---- C: layer 1 ----
        u64 acc[4][8];
#pragma unroll
        for (int u = 0; u < 4; u++)
#pragma unroll
            for (int e = 0; e < 8; e++) acc[u][e] = 0ull;
        {
            const float* inw = inb + (w * 8) * INP;     // warp-uniform
            const float* wb = w1t + lane * INP;
#pragma unroll 2
            for (int k4 = 0; k4 < DIN / 4; k4++) {
                ulonglong2 wf[4];
#pragma unroll
                for (int u = 0; u < 4; u++)
                    wf[u] = *(const ulonglong2*)(wb + u * 32 * INP + 4 * k4);
#pragma unroll
                for (int e = 0; e < 8; e++) {
                    ulonglong2 av = *(const ulonglong2*)(inw + e * INP + 4 * k4);
#pragma unroll
                    for (int u = 0; u < 4; u++) {
                        FMA2(acc[u][e], av.x, wf[u].x);
                        FMA2(acc[u][e], av.y, wf[u].y);
                    }
                }
            }
        }
        __syncthreads();   // all inb reads done before hid (alias) writes
        // ---- D: gelu + transposed store ----
#pragma unroll
        for (int e = 0; e < 8; e++)
#pragma unroll
            for (int u = 0; u < 4; u++) {
                int j = 32 * u + lane;
                hid[(w * 8 + e) * HP + j] = gelu_t(hadd2(acc[u][e]) + b1s[j]);
            }
        __syncthreads();
        // ---- E: layer 2 (lane owns j = lane, lane+32) ----
        u64 o0[8], o1[8];
#pragma unroll
        for (int e = 0; e < 8; e++) { o0[e] = 0ull; o1[e] = 0ull; }
        {
            const float* hw = hid + (w * 8) * HP;       // warp-uniform
            const float* wa = w2t + lane * W2P;
            const float* wbp = w2t + (lane + 32) * W2P;
#pragma unroll 2
            for (int k4 = 0; k4 < 32; k4++) {
                ulonglong2 va = *(const ulonglong2*)(wa + 4 * k4);
                ulonglong2 vb = *(const ulonglong2*)(wbp + 4 * k4);
#pragma unroll
                for (int e = 0; e < 8; e++) {
                    ulonglong2 av = *(const ulonglong2*)(hw + e * HP + 4 * k4);
                    FMA2(o0[e], av.x, va.x);
                    FMA2(o0[e], av.y, va.y);
                    FMA2(o1[e], av.x, vb.x);
                    FMA2(o1[e], av.y, vb.y);
                }
            }
        }
        // ---- F: scatter ----
#pragma unroll
        for (int e = 0; e < 8; e++) {
            int eid = ebase + w * 8 + e;
            if (eid < En) {
                int rc = ridx[w * 8 + e];
                float u0 = hadd2(o0[e]) + b2s[lane];
                float u1 = hadd2(o1[e]) + b2s[lane + 32];
                if (write_e) {
                    g_e[(size_t)eid * 64 + lane] = u0;
                    g_e[(size_t)eid * 64 + 32 + lane] = u1;
                }
                atomicAdd(&g_recv[(size_t)rc * 64 + lane], u0);
                atomicAdd(&g_recv[(size_t)rc * 64 + 32 + lane], u1);
            }
        }
        __syncthreads();   // hid/ridx reads done before next iter overwrites
    }
}

// ---------------------------------------------------------------------------
// Fused node MLP + residual + LayerNorm. DIN=144, same tiling.
// ---------------------------------------------------------------------------
__global__ __launch_bounds__(384, 1) void node_kernel(
    const float* __restrict__ gvec,
    const float* __restrict__ w1, const float* __restrict__ b1,
    const float* __restrict__ w2, const float* __restrict__ b2,
    const float* __restrict__ lnsc, const float* __restrict__ lnbi, int Nv) {
    constexpr int DIN = 144, INP = 148, W2P = 132, HP = 132, MB = 96, NT = 384, NC = 36;
    extern __shared__ float sm[];
    float* w1t = sm;
    float* w2t = w1t + 128 * INP;
    float* b1s = w2t + 64 * W2P;
    float* b2s = b1s + 128;
    float* gs  = b2s + 64;
    float* lns = gs + 16;
    float* lnb = lns + 64;
    float* inb = lnb + 64;
    float* hid = inb;                  // alias

    int tid = threadIdx.x;
    for (int i = tid; i < DIN * 128; i += NT) {
        int k = i >> 7, j = i & 127;
        w1t[j * INP + k] = w1[i];
    }
    for (int i = tid; i < 128 * 64; i += NT) {
        int k = i >> 6, j = i & 63;
        w2t[j * W2P + k] = w2[i];
    }
    if (tid < 128) b1s[tid] = b1[tid];
    else if (tid < 192) b2s[tid - 128] = b2[tid - 128];
    else if (tid < 208) gs[tid - 192] = gvec[tid - 192];
    for (int i = tid; i < 64; i += NT) { lns[i] = lnsc[i]; lnb[i] = lnbi[i]; }
    __syncthreads();

    int w = tid >> 5, lane = tid & 31;

    int nIter = (Nv + MB - 1) / MB;
    for (int it = blockIdx.x; it < nIter; it += gridDim.x) {
        int nbase = it * MB;
        // ---- gather ----
        {
            const float4* hp = (const float4*)g_h;
            const float4* rp = (const float4*)g_recv;
            const float4* gp4 = (const float4*)gs;
            for (int c = tid; c < MB * NC; c += NT) {
                int m = c / NC, q = c - m * NC;
                int nid = nbase + m; if (nid >= Nv) nid = Nv - 1;
                float4 v;
                if (q < 16)      v = hp[(size_t)nid * 16 + q];
                else if (q < 32) v = rp[(size_t)nid * 16 + (q - 16)];
                else             v = gp4[q - 32];
                ((float4*)(inb + m * INP))[q] = v;
            }
        }
        __syncthreads();
        // ---- layer 1 ----
        u64 acc[4][8];
#pragma unroll
        for (int u = 0; u < 4; u++)
#pragma unroll
            for (int e = 0; e < 8; e++) acc[u][e] = 0ull;
        {
            const float* inw = inb + (w * 8) * INP;
            const float* wb = w1t + lane * INP;
#pragma unroll 2
            for (int k4 = 0; k4 < DIN / 4; k4++) {
                ulonglong2 wf[4];
#pragma unroll
                for (int u = 0; u < 4; u++)
                    wf[u] = *(const ulonglong2*)(wb + u * 32 * INP + 4 * k4);
#pragma unroll
                for (int e = 0; e < 8; e++) {
                    ulonglong2 av = *(const ulonglong2*)(inw + e * INP + 4 * k4);
#pragma unroll
                    for (int u = 0; u < 4; u++) {
                        FMA2(acc[u][e], av.x, wf[u].x);
                        FMA2(acc[u][e], av.y, wf[u].y);
                    }
                }
            }
        }
        __syncthreads();
        // ---- gelu + transposed store ----
#pragma unroll
        for (int e = 0; e < 8; e++)
#pragma unroll
            for (int u = 0; u < 4; u++) {
                int j = 32 * u + lane;
                hid[(w * 8 + e) * HP + j] = gelu_t(hadd2(acc[u][e]) + b1s[j]);
            }
        __syncthreads();
        // ---- layer 2 ----
        u64 o0[8], o1[8];
#pragma unroll
        for (int e = 0; e < 8; e++) { o0[e] = 0ull; o1[e] = 0ull; }
        {
            const float* hw = hid + (w * 8) * HP;
            const float* wa = w2t + lane * W2P;
            const float* wbp = w2t + (lane + 32) * W2P;
#pragma unroll 2
            for (int k4 = 0; k4 < 32; k4++) {
                ulonglong2 va = *(const ulonglong2*)(wa + 4 * k4);
                ulonglong2 vb = *(const ulonglong2*)(wbp + 4 * k4);
#pragma unroll
                for (int e = 0; e < 8; e++) {
                    ulonglong2 av = *(const ulonglong2*)(hw + e * HP + 4 * k4);
                    FMA2(o0[e], av.x, va.x);
                    FMA2(o0[e], av.y, va.y);
                    FMA2(o1[e], av.x, vb.x);
                    FMA2(o1[e], av.y, vb.y);
                }
            }
        }
        // ---- residual + LayerNorm ----
#pragma unroll
        for (int e = 0; e < 8; e++) {
            int nid = nbase + w * 8 + e;
            int nc = nid < Nv ? nid : Nv - 1;
            float h0 = g_h[(size_t)nc * 64 + lane];
            float h1 = g_h[(size_t)nc * 64 + 32 + lane];
            float x0 = h0 + hadd2(o0[e]) + b2s[lane];
            float x1 = h1 + hadd2(o1[e]) + b2s[lane + 32];
            float s = x0 + x1, q = x0 * x0 + x1 * x1;
#pragma unroll
            for (int d = 16; d; d >>= 1) {
                s += __shfl_xor_sync(0xffffffffu, s, d);
                q += __shfl_xor_sync(0xffffffffu, q, d);
            }
            float mu = s * (1.0f / 64.0f);
            float var = q * (1.0f / 64.0f) - mu * mu;
            float inv = rsqrtf(var + 1e-6f);
            if (nid < Nv) {
                g_h[(size_t)nid * 64 + lane]      = (x0 - mu) * inv * lns[lane] + lnb[lane];
                g_h[(size_t)nid * 64 + 32 + lane] = (x1 - mu) * inv * lns[lane + 32] + lnb[lane + 32];
            }
        }
        __syncthreads();
    }
}

// ---------------------------------------------------------------------------
__global__ void decode_kernel(const float* __restrict__ dec_w,
                              const float* __restrict__ dec_b,
                              float* __restrict__ out, int Nv) {
    int gwarp = (blockIdx.x * blockDim.x + threadIdx.x) >> 5;
    int lane = threadIdx.x & 31;
    int nWarps = (gridDim.x * blockDim.x) >> 5;
    for (int n = gwarp; n < Nv; n += nWarps) {
        float h0 = g_h[n * 64 + lane];
        float h1 = g_h[n * 64 + 32 + lane];
        float p[7];
#pragma unroll
        for (int k = 0; k < 7; k++)
            p[k] = h0 * dec_w[lane * 7 + k] + h1 * dec_w[(lane + 32) * 7 + k];
#pragma unroll
        for (int k = 0; k < 7; k++)
#pragma unroll
            for (int d = 16; d; d >>= 1) p[k] += __shfl_xor_sync(0xffffffffu, p[k], d);
        if (lane < 7) out[n * 7 + lane] = p[lane] + dec_b[lane];
    }
}

// ---------------------------------------------------------------------------
extern "C" void kernel_launch(void* const* d_in, const int* in_sizes, int n_in,
                              void* d_out, int out_size) {
    const float* nodes   = (const float*)d_in[0];
    const int*   senders = (const int*)d_in[1];
    const int*   recvrs  = (const int*)d_in[2];
    const float* g       = (const float*)d_in[3];
    const float* embed_w = (const float*)d_in[4];
    const float* embed_b = (const float*)d_in[5];
    const float* ew1f    = (const float*)d_in[6];
    const float* ew1r    = (const float*)d_in[7];
    const float* eb1     = (const float*)d_in[8];
    const float* ew2     = (const float*)d_in[9];
    const float* eb2     = (const float*)d_in[10];
    const float* nw1     = (const float*)d_in[11];
    const float* nb1     = (const float*)d_in[12];
    const float* nw2     = (const float*)d_in[13];
    const float* nb2     = (const float*)d_in[14];
    const float* lnsc    = (const float*)d_in[15];
    const float* lnbi    = (const float*)d_in[16];
    const float* dec_w   = (const float*)d_in[17];
    const float* dec_b   = (const float*)d_in[18];
    float* out = (float*)d_out;

    int En = in_sizes[1];
    int Nv = in_sizes[0] / 7;

    // exact smem (floats): w1t + w2t + b1 + b2 + g + idx(2*MB ints) + inb(MB*INP)
    size_t sm_e0 = (size_t)(128 * 148 + 64 * 132 + 128 + 64 + 16 + 192 + 96 * 148) * 4;
    size_t sm_e1 = (size_t)(128 * 212 + 64 * 132 + 128 + 64 + 16 + 192 + 96 * 212) * 4;
    size_t sm_n  = (size_t)(128 * 148 + 64 * 132 + 128 + 64 + 16 + 64 + 64 + 96 * 148) * 4;

    cudaFuncSetAttribute(edge_kernel<144, false>,
                         cudaFuncAttributeMaxDynamicSharedMemorySize, (int)sm_e0);
    cudaFuncSetAttribute(edge_kernel<208, true>,
                         cudaFuncAttributeMaxDynamicSharedMemorySize, (int)sm_e1);
    cudaFuncSetAttribute(node_kernel,
                         cudaFuncAttributeMaxDynamicSharedMemorySize, (int)sm_n);

    const int GRID = 148;

    embed_kernel<<<(Nv * 64 + 255) / 256, 256>>>(nodes, embed_w, embed_b, Nv);

    for (int t = 0; t < 3; t++) {
        zero_recv_kernel<<<(Nv * 64 + 255) / 256, 256>>>(Nv * 64);
        if (t == 0) {
            edge_kernel<144, false><<<GRID, 384, sm_e0>>>(
                senders, recvrs, g, ew1f, eb1, ew2, eb2, En, 1);
        } else {
            edge_kernel<208, true><<<GRID, 384, sm_e1>>>(
                senders, recvrs, g,
                ew1r + (size_t)(t - 1) * 208 * 128,
                eb1 + t * 128, ew2 + (size_t)t * 128 * 64, eb2 + t * 64,
                En, (t == 2) ? 0 : 1);
        }
        node_kernel<<<GRID, 384, sm_n>>>(
            g, nw1 + (size_t)t * 144 * 128, nb1 + t * 128,
            nw2 + (size_t)t * 128 * 64, nb2 + t * 64,
            lnsc + t * 64, lnbi + t * 64, Nv);
    }

    decode_kernel<<<208, 256>>>(dec_w, dec_b, out, Nv);
}

// round 8
// speedup vs baseline: 1.7232x; 1.0271x over previous
#include <cuda_runtime.h>
#include <math.h>

#define NN 50000
#define EE 800000

__device__ float g_h[NN * 64];
__device__ float g_e[EE * 64];
__device__ float g_recv[NN * 64];

typedef unsigned long long u64;

#define FMA2(d, a, b) asm("fma.rn.f32x2 %0, %1, %2, %0;" : "+l"(d) : "l"(a), "l"(b))

__device__ __forceinline__ float hadd2(u64 v) {
    float lo, hi;
    asm("mov.b64 {%0, %1}, %2;" : "=f"(lo), "=f"(hi) : "l"(v));
    return lo + hi;
}

// jax.nn.gelu (approximate=True), tanh via exp (~1e-7 accurate)
__device__ __forceinline__ float gelu_t(float x) {
    float y = 0.7978845608028654f * (x + 0.044715f * x * x * x);
    float e = __expf(2.0f * y);
    float th = 1.0f - __fdividef(2.0f, e + 1.0f);
    return 0.5f * x * (1.0f + th);
}

// ---------------------------------------------------------------------------
__global__ void embed_kernel(const float* __restrict__ nodes,
                             const float* __restrict__ w,
                             const float* __restrict__ b, int Nv) {
    int idx = blockIdx.x * blockDim.x + threadIdx.x;
    if (idx >= Nv * 64) return;
    int n = idx >> 6, j = idx & 63;
    float a = b[j];
#pragma unroll
    for (int k = 0; k < 7; k++) a += nodes[n * 7 + k] * w[k * 64 + j];
    g_h[idx] = a;
}

__global__ void zero_recv_kernel(int n) {
    int i = blockIdx.x * blockDim.x + threadIdx.x;
    if (i < n) g_recv[i] = 0.0f;
}

// ---------------------------------------------------------------------------
// Fused edge MLP. 512 threads = 16 warps; CTA tile = 96 edges (6/warp).
// Weights: LDS.128, 32 distinct rows (conflict-free). Inputs: warp-uniform
// LDS.128 broadcast. hid aliases inb. ~75 live regs -> ptxas headroom for
// load hoisting under the 128-reg cap.
// ---------------------------------------------------------------------------
template <int DIN, bool HAS_E>
__global__ __launch_bounds__(512, 1) void edge_kernel(
    const int* __restrict__ senders, const int* __restrict__ receivers,
    const float* __restrict__ gvec,
    const float* __restrict__ w1, const float* __restrict__ b1,
    const float* __restrict__ w2, const float* __restrict__ b2,
    int En, int write_e) {
    constexpr int INP = DIN + 4;
    constexpr int W2P = 132;
    constexpr int HP = 132;
    constexpr int MB = 96;
    constexpr int NT = 512;
    constexpr int NC = DIN / 4;

    extern __shared__ float sm[];
    float* w1t = sm;                    // 128*INP [j][k]
    float* w2t = w1t + 128 * INP;       // 64*W2P  [j][k] k<128
    float* b1s = w2t + 64 * W2P;        // 128
    float* b2s = b1s + 128;             // 64
    float* gs  = b2s + 64;              // 16
    int* sidx  = (int*)(gs + 16);       // 96
    int* ridx  = sidx + MB;             // 96
    float* inb = (float*)(ridx + MB);   // MB*INP (16B-aligned)
    float* hid = inb;                   // alias: MB*HP

    int tid = threadIdx.x;
    for (int i = tid; i < DIN * 128; i += NT) {
        int k = i >> 7, j = i & 127;
        w1t[j * INP + k] = w1[i];
    }
    for (int i = tid; i < 128 * 64; i += NT) {
        int k = i >> 6, j = i & 63;
        w2t[j * W2P + k] = w2[i];
    }
    if (tid < 128) b1s[tid] = b1[tid];
    else if (tid < 192) b2s[tid - 128] = b2[tid - 128];
    else if (tid < 208) gs[tid - 192] = gvec[tid - 192];
    __syncthreads();

    int w = tid >> 5, lane = tid & 31;

    int nIter = (En + MB - 1) / MB;
    for (int it = blockIdx.x; it < nIter; it += gridDim.x) {
        int ebase = it * MB;
        // ---- A: indices ----
        if (tid < MB) {
            int e = ebase + tid; if (e >= En) e = En - 1;
            sidx[tid] = senders[e];
        } else if (tid < 2 * MB) {
            int e = ebase + tid - MB; if (e >= En) e = En - 1;
            ridx[tid - MB] = receivers[e];
        }
        __syncthreads();
        // ---- B: gather inputs ----
        {
            const float4* hp = (const float4*)g_h;
            const float4* gp4 = (const float4*)gs;
            for (int c = tid; c < MB * NC; c += NT) {
                int m = c / NC, q = c - m * NC;
                float4 v;
                if (HAS_E) {
                    int e = ebase + m; if (e >= En) e = En - 1;
                    if (q < 16)      v = ((const float4*)g_e)[(size_t)e * 16 + q];
                    else if (q < 32) v = hp[(size_t)sidx[m] * 16 + (q - 16)];
                    else if (q < 48) v = hp[(size_t)ridx[m] * 16 + (q - 32)];
                    else             v = gp4[q - 48];
                } else {
                    if (q < 16)      v = hp[(size_t)sidx[m] * 16 + q];
                    else if (q < 32) v = hp[(size_t)ridx[m] * 16 + (q - 16)];
                    else             v = gp4[q - 32];
                }
                ((float4*)(inb + m * INP))[q] = v;
            }
        }
        __syncthreads();
        // ---- C: layer 1 (6 edges x 128 j per warp) ----
        u64 acc[4][6];
#pragma unroll
        for (int u = 0; u < 4; u++)
#pragma unroll
            for (int e = 0; e < 6; e++) acc[u][e] = 0ull;
        {
            const float* inw = inb + (w * 6) * INP;     // warp-uniform
            const float* wb = w1t + lane * INP;
#pragma unroll 2
            for (int k4 = 0; k4 < DIN / 4; k4++) {
                ulonglong2 wf[4];
#pragma unroll
                for (int u = 0; u < 4; u++)
                    wf[u] = *(const ulonglong2*)(wb + u * 32 * INP + 4 * k4);
#pragma unroll
                for (int e = 0; e < 6; e++) {
                    ulonglong2 av = *(const ulonglong2*)(inw + e * INP + 4 * k4);
#pragma unroll
                    for (int u = 0; u < 4; u++) {
                        FMA2(acc[u][e], av.x, wf[u].x);
                        FMA2(acc[u][e], av.y, wf[u].y);
                    }
                }
            }
        }
        __syncthreads();   // all inb reads done before hid (alias) writes
        // ---- D: gelu + transposed store ----
#pragma unroll
        for (int e = 0; e < 6; e++)
#pragma unroll
            for (int u = 0; u < 4; u++) {
                int j = 32 * u + lane;
                hid[(w * 6 + e) * HP + j] = gelu_t(hadd2(acc[u][e]) + b1s[j]);
            }
        __syncthreads();
        // ---- E: layer 2 (lane owns j = lane, lane+32) ----
        u64 o0[6], o1[6];
#pragma unroll
        for (int e = 0; e < 6; e++) { o0[e] = 0ull; o1[e] = 0ull; }
        {
            const float* hw = hid + (w * 6) * HP;       // warp-uniform
            const float* wa = w2t + lane * W2P;
            const float* wbp = w2t + (lane + 32) * W2P;
#pragma unroll 2
            for (int k4 = 0; k4 < 32; k4++) {
                ulonglong2 va = *(const ulonglong2*)(wa + 4 * k4);
                ulonglong2 vb = *(const ulonglong2*)(wbp + 4 * k4);
#pragma unroll
                for (int e = 0; e < 6; e++) {
                    ulonglong2 av = *(const ulonglong2*)(hw + e * HP + 4 * k4);
                    FMA2(o0[e], av.x, va.x);
                    FMA2(o0[e], av.y, va.y);
                    FMA2(o1[e], av.x, vb.x);
                    FMA2(o1[e], av.y, vb.y);
                }
            }
        }
        // ---- F: scatter ----
#pragma unroll
        for (int e = 0; e < 6; e++) {
            int eid = ebase + w * 6 + e;
            if (eid < En) {
                int rc = ridx[w * 6 + e];
                float u0 = hadd2(o0[e]) + b2s[lane];
                float u1 = hadd2(o1[e]) + b2s[lane + 32];
                if (write_e) {
                    g_e[(size_t)eid * 64 + lane] = u0;
                    g_e[(size_t)eid * 64 + 32 + lane] = u1;
                }
                atomicAdd(&g_recv[(size_t)rc * 64 + lane], u0);
                atomicAdd(&g_recv[(size_t)rc * 64 + 32 + lane], u1);
            }
        }
        __syncthreads();   // hid/ridx reads done before next iter overwrites
    }
}

// ---------------------------------------------------------------------------
// Fused node MLP + residual + LayerNorm. DIN=144, same tiling.
// ---------------------------------------------------------------------------
__global__ __launch_bounds__(512, 1) void node_kernel(
    const float* __restrict__ gvec,
    const float* __restrict__ w1, const float* __restrict__ b1,
    const float* __restrict__ w2, const float* __restrict__ b2,
    const float* __restrict__ lnsc, const float* __restrict__ lnbi, int Nv) {
    constexpr int DIN = 144, INP = 148, W2P = 132, HP = 132, MB = 96, NT = 512, NC = 36;
    extern __shared__ float sm[];
    float* w1t = sm;
    float* w2t = w1t + 128 * INP;
    float* b1s = w2t + 64 * W2P;
    float* b2s = b1s + 128;
    float* gs  = b2s + 64;
    float* lns = gs + 16;
    float* lnb = lns + 64;
    float* inb = lnb + 64;
    float* hid = inb;                  // alias

    int tid = threadIdx.x;
    for (int i = tid; i < DIN * 128; i += NT) {
        int k = i >> 7, j = i & 127;
        w1t[j * INP + k] = w1[i];
    }
    for (int i = tid; i < 128 * 64; i += NT) {
        int k = i >> 6, j = i & 63;
        w2t[j * W2P + k] = w2[i];
    }
    if (tid < 128) b1s[tid] = b1[tid];
    else if (tid < 192) b2s[tid - 128] = b2[tid - 128];
    else if (tid < 208) gs[tid - 192] = gvec[tid - 192];
    for (int i = tid; i < 64; i += NT) { lns[i] = lnsc[i]; lnb[i] = lnbi[i]; }
    __syncthreads();

    int w = tid >> 5, lane = tid & 31;

    int nIter = (Nv + MB - 1) / MB;
    for (int it = blockIdx.x; it < nIter; it += gridDim.x) {
        int nbase = it * MB;
        // ---- gather ----
        {
            const float4* hp = (const float4*)g_h;
            const float4* rp = (const float4*)g_recv;
            const float4* gp4 = (const float4*)gs;
            for (int c = tid; c < MB * NC; c += NT) {
                int m = c / NC, q = c - m * NC;
                int nid = nbase + m; if (nid >= Nv) nid = Nv - 1;
                float4 v;
                if (q < 16)      v = hp[(size_t)nid * 16 + q];
                else if (q < 32) v = rp[(size_t)nid * 16 + (q - 16)];
                else             v = gp4[q - 32];
                ((float4*)(inb + m * INP))[q] = v;
            }
        }
        __syncthreads();
        // ---- layer 1 ----
        u64 acc[4][6];
#pragma unroll
        for (int u = 0; u < 4; u++)
#pragma unroll
            for (int e = 0; e < 6; e++) acc[u][e] = 0ull;
        {
            const float* inw = inb + (w * 6) * INP;
            const float* wb = w1t + lane * INP;
#pragma unroll 2
            for (int k4 = 0; k4 < DIN / 4; k4++) {
                ulonglong2 wf[4];
#pragma unroll
                for (int u = 0; u < 4; u++)
                    wf[u] = *(const ulonglong2*)(wb + u * 32 * INP + 4 * k4);
#pragma unroll
                for (int e = 0; e < 6; e++) {
                    ulonglong2 av = *(const ulonglong2*)(inw + e * INP + 4 * k4);
#pragma unroll
                    for (int u = 0; u < 4; u++) {
                        FMA2(acc[u][e], av.x, wf[u].x);
                        FMA2(acc[u][e], av.y, wf[u].y);
                    }
                }
            }
        }
        __syncthreads();
        // ---- gelu + transposed store ----
#pragma unroll
        for (int e = 0; e < 6; e++)
#pragma unroll
            for (int u = 0; u < 4; u++) {
                int j = 32 * u + lane;
                hid[(w * 6 + e) * HP + j] = gelu_t(hadd2(acc[u][e]) + b1s[j]);
            }
        __syncthreads();
        // ---- layer 2 ----
        u64 o0[6], o1[6];
#pragma unroll
        for (int e = 0; e < 6; e++) { o0[e] = 0ull; o1[e] = 0ull; }
        {
            const float* hw = hid + (w * 6) * HP;
            const float* wa = w2t + lane * W2P;
            const float* wbp = w2t + (lane + 32) * W2P;
#pragma unroll 2
            for (int k4 = 0; k4 < 32; k4++) {
                ulonglong2 va = *(const ulonglong2*)(wa + 4 * k4);
                ulonglong2 vb = *(const ulonglong2*)(wbp + 4 * k4);
#pragma unroll
                for (int e = 0; e < 6; e++) {
                    ulonglong2 av = *(const ulonglong2*)(hw + e * HP + 4 * k4);
                    FMA2(o0[e], av.x, va.x);
                    FMA2(o0[e], av.y, va.y);
                    FMA2(o1[e], av.x, vb.x);
                    FMA2(o1[e], av.y, vb.y);
                }
            }
        }
        // ---- residual + LayerNorm ----
#pragma unroll
        for (int e = 0; e < 6; e++) {
            int nid = nbase + w * 6 + e;
            int nc = nid < Nv ? nid : Nv - 1;
            float h0 = g_h[(size_t)nc * 64 + lane];
            float h1 = g_h[(size_t)nc * 64 + 32 + lane];
            float x0 = h0 + hadd2(o0[e]) + b2s[lane];
            float x1 = h1 + hadd2(o1[e]) + b2s[lane + 32];
            float s = x0 + x1, q = x0 * x0 + x1 * x1;
#pragma unroll
            for (int d = 16; d; d >>= 1) {
                s += __shfl_xor_sync(0xffffffffu, s, d);
                q += __shfl_xor_sync(0xffffffffu, q, d);
            }
            float mu = s * (1.0f / 64.0f);
            float var = q * (1.0f / 64.0f) - mu * mu;
            float inv = rsqrtf(var + 1e-6f);
            if (nid < Nv) {
                g_h[(size_t)nid * 64 + lane]      = (x0 - mu) * inv * lns[lane] + lnb[lane];
                g_h[(size_t)nid * 64 + 32 + lane] = (x1 - mu) * inv * lns[lane + 32] + lnb[lane + 32];
            }
        }
        __syncthreads();
    }
}

// ---------------------------------------------------------------------------
__global__ void decode_kernel(const float* __restrict__ dec_w,
                              const float* __restrict__ dec_b,
                              float* __restrict__ out, int Nv) {
    int gwarp = (blockIdx.x * blockDim.x + threadIdx.x) >> 5;
    int lane = threadIdx.x & 31;
    int nWarps = (gridDim.x * blockDim.x) >> 5;
    for (int n = gwarp; n < Nv; n += nWarps) {
        float h0 = g_h[n * 64 + lane];
        float h1 = g_h[n * 64 + 32 + lane];
        float p[7];
#pragma unroll
        for (int k = 0; k < 7; k++)
            p[k] = h0 * dec_w[lane * 7 + k] + h1 * dec_w[(lane + 32) * 7 + k];
#pragma unroll
        for (int k = 0; k < 7; k++)
#pragma unroll
            for (int d = 16; d; d >>= 1) p[k] += __shfl_xor_sync(0xffffffffu, p[k], d);
        if (lane < 7) out[n * 7 + lane] = p[lane] + dec_b[lane];
    }
}

// ---------------------------------------------------------------------------
extern "C" void kernel_launch(void* const* d_in, const int* in_sizes, int n_in,
                              void* d_out, int out_size) {
    const float* nodes   = (const float*)d_in[0];
    const int*   senders = (const int*)d_in[1];
    const int*   recvrs  = (const int*)d_in[2];
    const float* g       = (const float*)d_in[3];
    const float* embed_w = (const float*)d_in[4];
    const float* embed_b = (const float*)d_in[5];
    const float* ew1f    = (const float*)d_in[6];
    const float* ew1r    = (const float*)d_in[7];
    const float* eb1     = (const float*)d_in[8];
    const float* ew2     = (const float*)d_in[9];
    const float* eb2     = (const float*)d_in[10];
    const float* nw1     = (const float*)d_in[11];
    const float* nb1     = (const float*)d_in[12];
    const float* nw2     = (const float*)d_in[13];
    const float* nb2     = (const float*)d_in[14];
    const float* lnsc    = (const float*)d_in[15];
    const float* lnbi    = (const float*)d_in[16];
    const float* dec_w   = (const float*)d_in[17];
    const float* dec_b   = (const float*)d_in[18];
    float* out = (float*)d_out;

    int En = in_sizes[1];
    int Nv = in_sizes[0] / 7;

    // exact smem (floats)
    size_t sm_e0 = (size_t)(128 * 148 + 64 * 132 + 128 + 64 + 16 + 192 + 96 * 148) * 4;
    size_t sm_e1 = (size_t)(128 * 212 + 64 * 132 + 128 + 64 + 16 + 192 + 96 * 212) * 4;
    size_t sm_n  = (size_t)(128 * 148 + 64 * 132 + 128 + 64 + 16 + 64 + 64 + 96 * 148) * 4;

    cudaFuncSetAttribute(edge_kernel<144, false>,
                         cudaFuncAttributeMaxDynamicSharedMemorySize, (int)sm_e0);
    cudaFuncSetAttribute(edge_kernel<208, true>,
                         cudaFuncAttributeMaxDynamicSharedMemorySize, (int)sm_e1);
    cudaFuncSetAttribute(node_kernel,
                         cudaFuncAttributeMaxDynamicSharedMemorySize, (int)sm_n);

    const int GRID = 148;

    embed_kernel<<<(Nv * 64 + 255) / 256, 256>>>(nodes, embed_w, embed_b, Nv);

    for (int t = 0; t < 3; t++) {
        zero_recv_kernel<<<(Nv * 64 + 255) / 256, 256>>>(Nv * 64);
        if (t == 0) {
            edge_kernel<144, false><<<GRID, 512, sm_e0>>>(
                senders, recvrs, g, ew1f, eb1, ew2, eb2, En, 1);
        } else {
            edge_kernel<208, true><<<GRID, 512, sm_e1>>>(
                senders, recvrs, g,
                ew1r + (size_t)(t - 1) * 208 * 128,
                eb1 + t * 128, ew2 + (size_t)t * 128 * 64, eb2 + t * 64,
                En, (t == 2) ? 0 : 1);
        }
        node_kernel<<<GRID, 512, sm_n>>>(
            g, nw1 + (size_t)t * 144 * 128, nb1 + t * 128,
            nw2 + (size_t)t * 128 * 64, nb2 + t * 64,
            lnsc + t * 64, lnbi + t * 64, Nv);
    }

    decode_kernel<<<208, 256>>>(dec_w, dec_b, out, Nv);
}

// round 9
// speedup vs baseline: 1.7438x; 1.0119x over previous
#include <cuda_runtime.h>
#include <math.h>

#define NN 50000
#define EE 800000

__device__ float g_h[NN * 64];
__device__ float g_e[EE * 64];
__device__ float g_recv[NN * 64];

typedef unsigned long long u64;

#define FMA2(d, a, b) asm("fma.rn.f32x2 %0, %1, %2, %0;" : "+l"(d) : "l"(a), "l"(b))

__device__ __forceinline__ float hadd2(u64 v) {
    float lo, hi;
    asm("mov.b64 {%0, %1}, %2;" : "=f"(lo), "=f"(hi) : "l"(v));
    return lo + hi;
}

// jax.nn.gelu (approximate=True), tanh via exp (~1e-7 accurate)
__device__ __forceinline__ float gelu_t(float x) {
    float y = 0.7978845608028654f * (x + 0.044715f * x * x * x);
    float e = __expf(2.0f * y);
    float th = 1.0f - __fdividef(2.0f, e + 1.0f);
    return 0.5f * x * (1.0f + th);
}

// ---------------------------------------------------------------------------
__global__ void embed_kernel(const float* __restrict__ nodes,
                             const float* __restrict__ w,
                             const float* __restrict__ b, int Nv) {
    int idx = blockIdx.x * blockDim.x + threadIdx.x;
    if (idx >= Nv * 64) return;
    int n = idx >> 6, j = idx & 63;
    float a = b[j];
#pragma unroll
    for (int k = 0; k < 7; k++) a += nodes[n * 7 + k] * w[k * 64 + j];
    g_h[idx] = a;
}

__global__ void zero_recv_kernel(int n) {
    int i = blockIdx.x * blockDim.x + threadIdx.x;
    if (i < n) g_recv[i] = 0.0f;
}

// ---------------------------------------------------------------------------
// Fused edge MLP. 512 threads = 16 warps; CTA tile = 96 edges (6/warp).
// hid lives in OWN-WARP rows of inb (rows w*6..w*6+5 are private to warp w
// after the gather barrier), so layer1->gelu->layer2->scatter runs with NO
// CTA barriers: warps flow independently, covering each other's stalls.
// Only 3 barriers/tile: idx, gather, end-of-tile.
// ---------------------------------------------------------------------------
template <int DIN, bool HAS_E>
__global__ __launch_bounds__(512, 1) void edge_kernel(
    const int* __restrict__ senders, const int* __restrict__ receivers,
    const float* __restrict__ gvec,
    const float* __restrict__ w1, const float* __restrict__ b1,
    const float* __restrict__ w2, const float* __restrict__ b2,
    int En, int write_e) {
    constexpr int INP = DIN + 4;
    constexpr int W2P = 132;
    constexpr int MB = 96;
    constexpr int NT = 512;
    constexpr int NC = DIN / 4;

    extern __shared__ float sm[];
    float* w1t = sm;                    // 128*INP [j][k]
    float* w2t = w1t + 128 * INP;       // 64*W2P  [j][k] k<128
    float* b1s = w2t + 64 * W2P;        // 128
    float* b2s = b1s + 128;             // 64
    float* gs  = b2s + 64;              // 16
    int* sidx  = (int*)(gs + 16);       // 96
    int* ridx  = sidx + MB;             // 96
    float* inb = (float*)(ridx + MB);   // MB*INP ; rows double as hid

    int tid = threadIdx.x;
    for (int i = tid; i < DIN * 128; i += NT) {
        int k = i >> 7, j = i & 127;
        w1t[j * INP + k] = w1[i];
    }
    for (int i = tid; i < 128 * 64; i += NT) {
        int k = i >> 6, j = i & 63;
        w2t[j * W2P + k] = w2[i];
    }
    if (tid < 128) b1s[tid] = b1[tid];
    else if (tid < 192) b2s[tid - 128] = b2[tid - 128];
    else if (tid < 208) gs[tid - 192] = gvec[tid - 192];
    __syncthreads();

    int w = tid >> 5, lane = tid & 31;

    int nIter = (En + MB - 1) / MB;
    for (int it = blockIdx.x; it < nIter; it += gridDim.x) {
        int ebase = it * MB;
        // ---- A: indices ----
        if (tid < MB) {
            int e = ebase + tid; if (e >= En) e = En - 1;
            sidx[tid] = senders[e];
        } else if (tid < 2 * MB) {
            int e = ebase + tid - MB; if (e >= En) e = En - 1;
            ridx[tid - MB] = receivers[e];
        }
        __syncthreads();
        // ---- B: gather inputs ----
        {
            const float4* hp = (const float4*)g_h;
            const float4* gp4 = (const float4*)gs;
            for (int c = tid; c < MB * NC; c += NT) {
                int m = c / NC, q = c - m * NC;
                float4 v;
                if (HAS_E) {
                    int e = ebase + m; if (e >= En) e = En - 1;
                    if (q < 16)      v = ((const float4*)g_e)[(size_t)e * 16 + q];
                    else if (q < 32) v = hp[(size_t)sidx[m] * 16 + (q - 16)];
                    else if (q < 48) v = hp[(size_t)ridx[m] * 16 + (q - 32)];
                    else             v = gp4[q - 48];
                } else {
                    if (q < 16)      v = hp[(size_t)sidx[m] * 16 + q];
                    else if (q < 32) v = hp[(size_t)ridx[m] * 16 + (q - 16)];
                    else             v = gp4[q - 32];
                }
                ((float4*)(inb + m * INP))[q] = v;
            }
        }
        __syncthreads();
        // ---- C: layer 1 (6 edges x 128 j per warp) ----
        u64 acc[4][6];
#pragma unroll
        for (int u = 0; u < 4; u++)
#pragma unroll
            for (int e = 0; e < 6; e++) acc[u][e] = 0ull;
        {
            const float* inw = inb + (w * 6) * INP;     // warp-uniform
            const float* wb = w1t + lane * INP;
#pragma unroll 2
            for (int k4 = 0; k4 < DIN / 4; k4++) {
                ulonglong2 wf[4];
#pragma unroll
                for (int u = 0; u < 4; u++)
                    wf[u] = *(const ulonglong2*)(wb + u * 32 * INP + 4 * k4);
#pragma unroll
                for (int e = 0; e < 6; e++) {
                    ulonglong2 av = *(const ulonglong2*)(inw + e * INP + 4 * k4);
#pragma unroll
                    for (int u = 0; u < 4; u++) {
                        FMA2(acc[u][e], av.x, wf[u].x);
                        FMA2(acc[u][e], av.y, wf[u].y);
                    }
                }
            }
        }
        // ---- D: gelu + store into OWN rows of inb (no barrier needed) ----
        {
            float* hidw = inb + (w * 6) * INP;
#pragma unroll
            for (int e = 0; e < 6; e++)
#pragma unroll
                for (int u = 0; u < 4; u++) {
                    int j = 32 * u + lane;
                    hidw[e * INP + j] = gelu_t(hadd2(acc[u][e]) + b1s[j]);
                }
        }
        __syncwarp();
        // ---- E: layer 2 (lane owns j = lane, lane+32) ----
        u64 o0[6], o1[6];
#pragma unroll
        for (int e = 0; e < 6; e++) { o0[e] = 0ull; o1[e] = 0ull; }
        {
            const float* hw = inb + (w * 6) * INP;      // warp-uniform
            const float* wa = w2t + lane * W2P;
            const float* wbp = w2t + (lane + 32) * W2P;
#pragma unroll 2
            for (int k4 = 0; k4 < 32; k4++) {
                ulonglong2 va = *(const ulonglong2*)(wa + 4 * k4);
                ulonglong2 vb = *(const ulonglong2*)(wbp + 4 * k4);
#pragma unroll
                for (int e = 0; e < 6; e++) {
                    ulonglong2 av = *(const ulonglong2*)(hw + e * INP + 4 * k4);
                    FMA2(o0[e], av.x, va.x);
                    FMA2(o0[e], av.y, va.y);
                    FMA2(o1[e], av.x, vb.x);
                    FMA2(o1[e], av.y, vb.y);
                }
            }
        }
        // ---- F: scatter ----
#pragma unroll
        for (int e = 0; e < 6; e++) {
            int eid = ebase + w * 6 + e;
            if (eid < En) {
                int rc = ridx[w * 6 + e];
                float u0 = hadd2(o0[e]) + b2s[lane];
                float u1 = hadd2(o1[e]) + b2s[lane + 32];
                if (write_e) {
                    g_e[(size_t)eid * 64 + lane] = u0;
                    g_e[(size_t)eid * 64 + 32 + lane] = u1;
                }
                atomicAdd(&g_recv[(size_t)rc * 64 + lane], u0);
                atomicAdd(&g_recv[(size_t)rc * 64 + 32 + lane], u1);
            }
        }
        __syncthreads();   // inb/idx reads done before next tile overwrites
    }
}

// ---------------------------------------------------------------------------
// Fused node MLP + residual + LayerNorm. DIN=144, same barrier-free pipeline.
// ---------------------------------------------------------------------------
__global__ __launch_bounds__(512, 1) void node_kernel(
    const float* __restrict__ gvec,
    const float* __restrict__ w1, const float* __restrict__ b1,
    const float* __restrict__ w2, const float* __restrict__ b2,
    const float* __restrict__ lnsc, const float* __restrict__ lnbi, int Nv) {
    constexpr int DIN = 144, INP = 148, W2P = 132, MB = 96, NT = 512, NC = 36;
    extern __shared__ float sm[];
    float* w1t = sm;
    float* w2t = w1t + 128 * INP;
    float* b1s = w2t + 64 * W2P;
    float* b2s = b1s + 128;
    float* gs  = b2s + 64;
    float* lns = gs + 16;
    float* lnb = lns + 64;
    float* inb = lnb + 64;

    int tid = threadIdx.x;
    for (int i = tid; i < DIN * 128; i += NT) {
        int k = i >> 7, j = i & 127;
        w1t[j * INP + k] = w1[i];
    }
    for (int i = tid; i < 128 * 64; i += NT) {
        int k = i >> 6, j = i & 63;
        w2t[j * W2P + k] = w2[i];
    }
    if (tid < 128) b1s[tid] = b1[tid];
    else if (tid < 192) b2s[tid - 128] = b2[tid - 128];
    else if (tid < 208) gs[tid - 192] = gvec[tid - 192];
    for (int i = tid; i < 64; i += NT) { lns[i] = lnsc[i]; lnb[i] = lnbi[i]; }
    __syncthreads();

    int w = tid >> 5, lane = tid & 31;

    int nIter = (Nv + MB - 1) / MB;
    for (int it = blockIdx.x; it < nIter; it += gridDim.x) {
        int nbase = it * MB;
        // ---- gather ----
        {
            const float4* hp = (const float4*)g_h;
            const float4* rp = (const float4*)g_recv;
            const float4* gp4 = (const float4*)gs;
            for (int c = tid; c < MB * NC; c += NT) {
                int m = c / NC, q = c - m * NC;
                int nid = nbase + m; if (nid >= Nv) nid = Nv - 1;
                float4 v;
                if (q < 16)      v = hp[(size_t)nid * 16 + q];
                else if (q < 32) v = rp[(size_t)nid * 16 + (q - 16)];
                else             v = gp4[q - 32];
                ((float4*)(inb + m * INP))[q] = v;
            }
        }
        __syncthreads();
        // ---- layer 1 ----
        u64 acc[4][6];
#pragma unroll
        for (int u = 0; u < 4; u++)
#pragma unroll
            for (int e = 0; e < 6; e++) acc[u][e] = 0ull;
        {
            const float* inw = inb + (w * 6) * INP;
            const float* wb = w1t + lane * INP;
#pragma unroll 2
            for (int k4 = 0; k4 < DIN / 4; k4++) {
                ulonglong2 wf[4];
#pragma unroll
                for (int u = 0; u < 4; u++)
                    wf[u] = *(const ulonglong2*)(wb + u * 32 * INP + 4 * k4);
#pragma unroll
                for (int e = 0; e < 6; e++) {
                    ulonglong2 av = *(const ulonglong2*)(inw + e * INP + 4 * k4);
#pragma unroll
                    for (int u = 0; u < 4; u++) {
                        FMA2(acc[u][e], av.x, wf[u].x);
                        FMA2(acc[u][e], av.y, wf[u].y);
                    }
                }
            }
        }
        // ---- gelu + store into own rows (no barrier) ----
        {
            float* hidw = inb + (w * 6) * INP;
#pragma unroll
            for (int e = 0; e < 6; e++)
#pragma unroll
                for (int u = 0; u < 4; u++) {
                    int j = 32 * u + lane;
                    hidw[e * INP + j] = gelu_t(hadd2(acc[u][e]) + b1s[j]);
                }
        }
        __syncwarp();
        // ---- layer 2 ----
        u64 o0[6], o1[6];
#pragma unroll
        for (int e = 0; e < 6; e++) { o0[e] = 0ull; o1[e] = 0ull; }
        {
            const float* hw = inb + (w * 6) * INP;
            const float* wa = w2t + lane * W2P;
            const float* wbp = w2t + (lane + 32) * W2P;
#pragma unroll 2
            for (int k4 = 0; k4 < 32; k4++) {
                ulonglong2 va = *(const ulonglong2*)(wa + 4 * k4);
                ulonglong2 vb = *(const ulonglong2*)(wbp + 4 * k4);
#pragma unroll
                for (int e = 0; e < 6; e++) {
                    ulonglong2 av = *(const ulonglong2*)(hw + e * INP + 4 * k4);
                    FMA2(o0[e], av.x, va.x);
                    FMA2(o0[e], av.y, va.y);
                    FMA2(o1[e], av.x, vb.x);
                    FMA2(o1[e], av.y, vb.y);
                }
            }
        }
        // ---- residual + LayerNorm ----
#pragma unroll
        for (int e = 0; e < 6; e++) {
            int nid = nbase + w * 6 + e;
            int nc = nid < Nv ? nid : Nv - 1;
            float h0 = g_h[(size_t)nc * 64 + lane];
            float h1 = g_h[(size_t)nc * 64 + 32 + lane];
            float x0 = h0 + hadd2(o0[e]) + b2s[lane];
            float x1 = h1 + hadd2(o1[e]) + b2s[lane + 32];
            float s = x0 + x1, q = x0 * x0 + x1 * x1;
#pragma unroll
            for (int d = 16; d; d >>= 1) {
                s += __shfl_xor_sync(0xffffffffu, s, d);
                q += __shfl_xor_sync(0xffffffffu, q, d);
            }
            float mu = s * (1.0f / 64.0f);
            float var = q * (1.0f / 64.0f) - mu * mu;
            float inv = rsqrtf(var + 1e-6f);
            if (nid < Nv) {
                g_h[(size_t)nid * 64 + lane]      = (x0 - mu) * inv * lns[lane] + lnb[lane];
                g_h[(size_t)nid * 64 + 32 + lane] = (x1 - mu) * inv * lns[lane + 32] + lnb[lane + 32];
            }
        }
        __syncthreads();   // inb reads done before next gather
    }
}

// ---------------------------------------------------------------------------
__global__ void decode_kernel(const float* __restrict__ dec_w,
                              const float* __restrict__ dec_b,
                              float* __restrict__ out, int Nv) {
    int gwarp = (blockIdx.x * blockDim.x + threadIdx.x) >> 5;
    int lane = threadIdx.x & 31;
    int nWarps = (gridDim.x * blockDim.x) >> 5;
    for (int n = gwarp; n < Nv; n += nWarps) {
        float h0 = g_h[n * 64 + lane];
        float h1 = g_h[n * 64 + 32 + lane];
        float p[7];
#pragma unroll
        for (int k = 0; k < 7; k++)
            p[k] = h0 * dec_w[lane * 7 + k] + h1 * dec_w[(lane + 32) * 7 + k];
#pragma unroll
        for (int k = 0; k < 7; k++)
#pragma unroll
            for (int d = 16; d; d >>= 1) p[k] += __shfl_xor_sync(0xffffffffu, p[k], d);
        if (lane < 7) out[n * 7 + lane] = p[lane] + dec_b[lane];
    }
}

// ---------------------------------------------------------------------------
extern "C" void kernel_launch(void* const* d_in, const int* in_sizes, int n_in,
                              void* d_out, int out_size) {
    const float* nodes   = (const float*)d_in[0];
    const int*   senders = (const int*)d_in[1];
    const int*   recvrs  = (const int*)d_in[2];
    const float* g       = (const float*)d_in[3];
    const float* embed_w = (const float*)d_in[4];
    const float* embed_b = (const float*)d_in[5];
    const float* ew1f    = (const float*)d_in[6];
    const float* ew1r    = (const float*)d_in[7];
    const float* eb1     = (const float*)d_in[8];
    const float* ew2     = (const float*)d_in[9];
    const float* eb2     = (const float*)d_in[10];
    const float* nw1     = (const float*)d_in[11];
    const float* nb1     = (const float*)d_in[12];
    const float* nw2     = (const float*)d_in[13];
    const float* nb2     = (const float*)d_in[14];
    const float* lnsc    = (const float*)d_in[15];
    const float* lnbi    = (const float*)d_in[16];
    const float* dec_w   = (const float*)d_in[17];
    const float* dec_b   = (const float*)d_in[18];
    float* out = (float*)d_out;

    int En = in_sizes[1];
    int Nv = in_sizes[0] / 7;

    size_t sm_e0 = (size_t)(128 * 148 + 64 * 132 + 128 + 64 + 16 + 192 + 96 * 148) * 4;
    size_t sm_e1 = (size_t)(128 * 212 + 64 * 132 + 128 + 64 + 16 + 192 + 96 * 212) * 4;
    size_t sm_n  = (size_t)(128 * 148 + 64 * 132 + 128 + 64 + 16 + 64 + 64 + 96 * 148) * 4;

    cudaFuncSetAttribute(edge_kernel<144, false>,
                         cudaFuncAttributeMaxDynamicSharedMemorySize, (int)sm_e0);
    cudaFuncSetAttribute(edge_kernel<208, true>,
                         cudaFuncAttributeMaxDynamicSharedMemorySize, (int)sm_e1);
    cudaFuncSetAttribute(node_kernel,
                         cudaFuncAttributeMaxDynamicSharedMemorySize, (int)sm_n);

    const int GRID = 148;
    const int GRID_N = 131;  // 521 node tiles -> ~4/CTA balanced

    embed_kernel<<<(Nv * 64 + 255) / 256, 256>>>(nodes, embed_w, embed_b, Nv);

    for (int t = 0; t < 3; t++) {
        zero_recv_kernel<<<(Nv * 64 + 255) / 256, 256>>>(Nv * 64);
        if (t == 0) {
            edge_kernel<144, false><<<GRID, 512, sm_e0>>>(
                senders, recvrs, g, ew1f, eb1, ew2, eb2, En, 1);
        } else {
            edge_kernel<208, true><<<GRID, 512, sm_e1>>>(
                senders, recvrs, g,
                ew1r + (size_t)(t - 1) * 208 * 128,
                eb1 + t * 128, ew2 + (size_t)t * 128 * 64, eb2 + t * 64,
                En, (t == 2) ? 0 : 1);
        }
        node_kernel<<<GRID_N, 512, sm_n>>>(
            g, nw1 + (size_t)t * 144 * 128, nb1 + t * 128,
            nw2 + (size_t)t * 128 * 64, nb2 + t * 64,
            lnsc + t * 64, lnbi + t * 64, Nv);
    }

    decode_kernel<<<208, 256>>>(dec_w, dec_b, out, Nv);
}

// round 10
// speedup vs baseline: 3.5825x; 2.0544x over previous
#include <cuda_runtime.h>
#include <math.h>

#define NN 50000
#define EE 800000

__device__ float g_h[NN * 64];
__device__ float g_e[EE * 64];
__device__ float g_recv[NN * 64];
__device__ float g_hs[NN * 128];   // per-node sender-term (+ bias + g-term)
__device__ float g_hr[NN * 128];   // per-node receiver-term
__device__ float g_c[128];         // c = b1 + g @ w1_g

typedef unsigned long long u64;

#define FMA2(d, a, b) asm("fma.rn.f32x2 %0, %1, %2, %0;" : "+l"(d) : "l"(a), "l"(b))

__device__ __forceinline__ u64 pack_lo(float v) {
    u64 d; float z = 0.0f;
    asm("mov.b64 %0, {%1, %2};" : "=l"(d) : "f"(v), "f"(z));
    return d;
}

__device__ __forceinline__ float hadd2(u64 v) {
    float lo, hi;
    asm("mov.b64 {%0, %1}, %2;" : "=f"(lo), "=f"(hi) : "l"(v));
    return lo + hi;
}

// jax.nn.gelu (approximate=True), tanh via exp (~1e-7 accurate)
__device__ __forceinline__ float gelu_t(float x) {
    float y = 0.7978845608028654f * (x + 0.044715f * x * x * x);
    float e = __expf(2.0f * y);
    float th = 1.0f - __fdividef(2.0f, e + 1.0f);
    return 0.5f * x * (1.0f + th);
}

// ---------------------------------------------------------------------------
__global__ void embed_kernel(const float* __restrict__ nodes,
                             const float* __restrict__ w,
                             const float* __restrict__ b, int Nv) {
    int idx = blockIdx.x * blockDim.x + threadIdx.x;
    if (idx >= Nv * 64) return;
    int n = idx >> 6, j = idx & 63;
    float a = b[j];
#pragma unroll
    for (int k = 0; k < 7; k++) a += nodes[n * 7 + k] * w[k * 64 + j];
    g_h[idx] = a;
}

__global__ void zero_recv_kernel(int n) {
    int i = blockIdx.x * blockDim.x + threadIdx.x;
    if (i < n) g_recv[i] = 0.0f;
}

// c[j] = b1[j] + sum_k g[k] * w1g[k][j]
__global__ void const_kernel(const float* __restrict__ gvec,
                             const float* __restrict__ w1g,
                             const float* __restrict__ b1, int gdim) {
    int j = threadIdx.x;  // 128
    float a = b1[j];
    for (int k = 0; k < gdim; k++) a += gvec[k] * w1g[k * 128 + j];
    g_c[j] = a;
}

// ---------------------------------------------------------------------------
// Per-node precompute: hs = h @ w1s + c ; hr = h @ w1r.  w1s/w1r are [64,128].
// 512 thr, warp = 6 nodes, grid-stride by warp.
// ---------------------------------------------------------------------------
__global__ __launch_bounds__(512, 1) void pre_kernel(
    const float* __restrict__ w1s, const float* __restrict__ w1r, int Nv) {
    constexpr int WP = 68, HB = 68;
    extern __shared__ float sm[];
    float* wst  = sm;               // 128*68 [j][k]
    float* wrt  = wst + 128 * WP;   // 128*68
    float* hbuf = wrt + 128 * WP;   // 16*6*68

    int tid = threadIdx.x;
    for (int i = tid; i < 64 * 128; i += 512) {
        int k = i >> 7, j = i & 127;
        wst[j * WP + k] = w1s[i];
        wrt[j * WP + k] = w1r[i];
    }
    __syncthreads();

    int w = tid >> 5, lane = tid & 31;
    float* hb = hbuf + w * 6 * HB;
    int gw = blockIdx.x * 16 + w, stride = gridDim.x * 16;
    int nTiles = (Nv + 5) / 6;

    for (int tile = gw; tile < nTiles; tile += stride) {
        int nbase = tile * 6;
        for (int i = lane; i < 96; i += 32) {
            int e = i >> 4, q = i & 15;
            int nid = nbase + e; if (nid >= Nv) nid = Nv - 1;
            ((float4*)(hb + e * HB))[q] = ((const float4*)g_h)[(size_t)nid * 16 + q];
        }
        __syncwarp();
        // ---- hs pass (init with c) ----
        u64 acc[4][6];
#pragma unroll
        for (int u = 0; u < 4; u++) {
            float c = g_c[32 * u + lane];
#pragma unroll
            for (int e = 0; e < 6; e++) acc[u][e] = pack_lo(c);
        }
        {
            const float* wb = wst + lane * WP;
#pragma unroll 2
            for (int k4 = 0; k4 < 16; k4++) {
                ulonglong2 wf[4];
#pragma unroll
                for (int u = 0; u < 4; u++)
                    wf[u] = *(const ulonglong2*)(wb + u * 32 * WP + 4 * k4);
#pragma unroll
                for (int e = 0; e < 6; e++) {
                    ulonglong2 av = *(const ulonglong2*)(hb + e * HB + 4 * k4);
#pragma unroll
                    for (int u = 0; u < 4; u++) {
                        FMA2(acc[u][e], av.x, wf[u].x);
                        FMA2(acc[u][e], av.y, wf[u].y);
                    }
                }
            }
        }
#pragma unroll
        for (int e = 0; e < 6; e++) {
            int nid = nbase + e;
            if (nid < Nv)
#pragma unroll
                for (int u = 0; u < 4; u++)
                    g_hs[(size_t)nid * 128 + 32 * u + lane] = hadd2(acc[u][e]);
        }
        // ---- hr pass (init 0) ----
#pragma unroll
        for (int u = 0; u < 4; u++)
#pragma unroll
            for (int e = 0; e < 6; e++) acc[u][e] = 0ull;
        {
            const float* wb = wrt + lane * WP;
#pragma unroll 2
            for (int k4 = 0; k4 < 16; k4++) {
                ulonglong2 wf[4];
#pragma unroll
                for (int u = 0; u < 4; u++)
                    wf[u] = *(const ulonglong2*)(wb + u * 32 * WP + 4 * k4);
#pragma unroll
                for (int e = 0; e < 6; e++) {
                    ulonglong2 av = *(const ulonglong2*)(hb + e * HB + 4 * k4);
#pragma unroll
                    for (int u = 0; u < 4; u++) {
                        FMA2(acc[u][e], av.x, wf[u].x);
                        FMA2(acc[u][e], av.y, wf[u].y);
                    }
                }
            }
        }
#pragma unroll
        for (int e = 0; e < 6; e++) {
            int nid = nbase + e;
            if (nid < Nv)
#pragma unroll
                for (int u = 0; u < 4; u++)
                    g_hr[(size_t)nid * 128 + 32 * u + lane] = hadd2(acc[u][e]);
        }
        __syncwarp();
    }
}

// ---------------------------------------------------------------------------
// Edge MLP with factored layer 1: hidden = gelu(hs[s] + hr[r] + (e@w1e)).
// Warp-private tiles of 6 edges, grid-stride; NO in-loop CTA barriers.
// ---------------------------------------------------------------------------
template <bool HAS_E>
__global__ __launch_bounds__(512, 1) void edge_kernel(
    const int* __restrict__ senders, const int* __restrict__ receivers,
    const float* __restrict__ w1e, const float* __restrict__ w2,
    const float* __restrict__ b2, int En, int write_e) {
    constexpr int W1P = 68, EBP = 68, HP = 132, W2P = 132;
    extern __shared__ float sm[];
    float* w2t  = sm;                              // 64*132 [j][k] k<128
    float* b2s  = w2t + 64 * W2P;                  // 64
    float* w1t  = b2s + 64;                        // HAS_E: 128*68 [j][k] k<64
    float* ebuf = w1t + (HAS_E ? 128 * W1P : 0);   // HAS_E: 16*6*68
    float* hid  = ebuf + (HAS_E ? 16 * 6 * EBP : 0); // 16*6*132

    int tid = threadIdx.x;
    for (int i = tid; i < 128 * 64; i += 512) {
        int k = i >> 6, j = i & 63;
        w2t[j * W2P + k] = w2[i];
    }
    if (HAS_E)
        for (int i = tid; i < 64 * 128; i += 512) {
            int k = i >> 7, j = i & 127;
            w1t[j * W1P + k] = w1e[i];
        }
    if (tid < 64) b2s[tid] = b2[tid];
    __syncthreads();

    int w = tid >> 5, lane = tid & 31;
    float* eb = ebuf + w * 6 * EBP;
    float* hidw = hid + w * 6 * HP;
    int gw = blockIdx.x * 16 + w, stride = gridDim.x * 16;
    int nTiles = (En + 5) / 6;

    for (int tile = gw; tile < nTiles; tile += stride) {
        int ebase = tile * 6;
        int se[6], re[6];
#pragma unroll
        for (int e = 0; e < 6; e++) {
            int eid = ebase + e; if (eid >= En) eid = En - 1;
            se[e] = senders[eid];
            re[e] = receivers[eid];
        }
        if (HAS_E) {
            for (int i = lane; i < 96; i += 32) {
                int e = i >> 4, q = i & 15;
                int eid = ebase + e; if (eid >= En) eid = En - 1;
                ((float4*)(eb + e * EBP))[q] = ((const float4*)g_e)[(size_t)eid * 16 + q];
            }
            __syncwarp();
        }
        // ---- layer 1: init from hs/hr gathers, then optional e@w1e ----
        u64 acc[4][6];
#pragma unroll
        for (int u = 0; u < 4; u++) {
            int j = 32 * u + lane;
#pragma unroll
            for (int e = 0; e < 6; e++) {
                float v = g_hs[(size_t)se[e] * 128 + j] + g_hr[(size_t)re[e] * 128 + j];
                acc[u][e] = pack_lo(v);
            }
        }
        if (HAS_E) {
            const float* wb = w1t + lane * W1P;
#pragma unroll 2
            for (int k4 = 0; k4 < 16; k4++) {
                ulonglong2 wf[4];
#pragma unroll
                for (int u = 0; u < 4; u++)
                    wf[u] = *(const ulonglong2*)(wb + u * 32 * W1P + 4 * k4);
#pragma unroll
                for (int e = 0; e < 6; e++) {
                    ulonglong2 av = *(const ulonglong2*)(eb + e * EBP + 4 * k4);
#pragma unroll
                    for (int u = 0; u < 4; u++) {
                        FMA2(acc[u][e], av.x, wf[u].x);
                        FMA2(acc[u][e], av.y, wf[u].y);
                    }
                }
            }
        }
        // ---- gelu into own-warp smem rows ----
#pragma unroll
        for (int e = 0; e < 6; e++)
#pragma unroll
            for (int u = 0; u < 4; u++) {
                int j = 32 * u + lane;
                hidw[e * HP + j] = gelu_t(hadd2(acc[u][e]));
            }
        __syncwarp();
        // ---- layer 2 ----
        u64 o0[6], o1[6];
#pragma unroll
        for (int e = 0; e < 6; e++) { o0[e] = 0ull; o1[e] = 0ull; }
        {
            const float* wa = w2t + lane * W2P;
            const float* wbp = w2t + (lane + 32) * W2P;
#pragma unroll 2
            for (int k4 = 0; k4 < 32; k4++) {
                ulonglong2 va = *(const ulonglong2*)(wa + 4 * k4);
                ulonglong2 vb = *(const ulonglong2*)(wbp + 4 * k4);
#pragma unroll
                for (int e = 0; e < 6; e++) {
                    ulonglong2 av = *(const ulonglong2*)(hidw + e * HP + 4 * k4);
                    FMA2(o0[e], av.x, va.x);
                    FMA2(o0[e], av.y, va.y);
                    FMA2(o1[e], av.x, vb.x);
                    FMA2(o1[e], av.y, vb.y);
                }
            }
        }
        // ---- scatter ----
#pragma unroll
        for (int e = 0; e < 6; e++) {
            int eid = ebase + e;
            if (eid < En) {
                float u0 = hadd2(o0[e]) + b2s[lane];
                float u1 = hadd2(o1[e]) + b2s[lane + 32];
                if (write_e) {
                    g_e[(size_t)eid * 64 + lane] = u0;
                    g_e[(size_t)eid * 64 + 32 + lane] = u1;
                }
                atomicAdd(&g_recv[(size_t)re[e] * 64 + lane], u0);
                atomicAdd(&g_recv[(size_t)re[e] * 64 + 32 + lane], u1);
            }
        }
        __syncwarp();
    }
}

// ---------------------------------------------------------------------------
// Fused node MLP + residual + LayerNorm (unchanged from R9).
// ---------------------------------------------------------------------------
__global__ __launch_bounds__(512, 1) void node_kernel(
    const float* __restrict__ gvec,
    const float* __restrict__ w1, const float* __restrict__ b1,
    const float* __restrict__ w2, const float* __restrict__ b2,
    const float* __restrict__ lnsc, const float* __restrict__ lnbi, int Nv) {
    constexpr int DIN = 144, INP = 148, W2P = 132, MB = 96, NT = 512, NC = 36;
    extern __shared__ float sm[];
    float* w1t = sm;
    float* w2t = w1t + 128 * INP;
    float* b1s = w2t + 64 * W2P;
    float* b2s = b1s + 128;
    float* gs  = b2s + 64;
    float* lns = gs + 16;
    float* lnb = lns + 64;
    float* inb = lnb + 64;

    int tid = threadIdx.x;
    for (int i = tid; i < DIN * 128; i += NT) {
        int k = i >> 7, j = i & 127;
        w1t[j * INP + k] = w1[i];
    }
    for (int i = tid; i < 128 * 64; i += NT) {
        int k = i >> 6, j = i & 63;
        w2t[j * W2P + k] = w2[i];
    }
    if (tid < 128) b1s[tid] = b1[tid];
    else if (tid < 192) b2s[tid - 128] = b2[tid - 128];
    else if (tid < 208) gs[tid - 192] = gvec[tid - 192];
    for (int i = tid; i < 64; i += NT) { lns[i] = lnsc[i]; lnb[i] = lnbi[i]; }
    __syncthreads();

    int w = tid >> 5, lane = tid & 31;

    int nIter = (Nv + MB - 1) / MB;
    for (int it = blockIdx.x; it < nIter; it += gridDim.x) {
        int nbase = it * MB;
        {
            const float4* hp = (const float4*)g_h;
            const float4* rp = (const float4*)g_recv;
            const float4* gp4 = (const float4*)gs;
            for (int c = tid; c < MB * NC; c += NT) {
                int m = c / NC, q = c - m * NC;
                int nid = nbase + m; if (nid >= Nv) nid = Nv - 1;
                float4 v;
                if (q < 16)      v = hp[(size_t)nid * 16 + q];
                else if (q < 32) v = rp[(size_t)nid * 16 + (q - 16)];
                else             v = gp4[q - 32];
                ((float4*)(inb + m * INP))[q] = v;
            }
        }
        __syncthreads();
        u64 acc[4][6];
#pragma unroll
        for (int u = 0; u < 4; u++)
#pragma unroll
            for (int e = 0; e < 6; e++) acc[u][e] = 0ull;
        {
            const float* inw = inb + (w * 6) * INP;
            const float* wb = w1t + lane * INP;
#pragma unroll 2
            for (int k4 = 0; k4 < DIN / 4; k4++) {
                ulonglong2 wf[4];
#pragma unroll
                for (int u = 0; u < 4; u++)
                    wf[u] = *(const ulonglong2*)(wb + u * 32 * INP + 4 * k4);
#pragma unroll
                for (int e = 0; e < 6; e++) {
                    ulonglong2 av = *(const ulonglong2*)(inw + e * INP + 4 * k4);
#pragma unroll
                    for (int u = 0; u < 4; u++) {
                        FMA2(acc[u][e], av.x, wf[u].x);
                        FMA2(acc[u][e], av.y, wf[u].y);
                    }
                }
            }
        }
        {
            float* hidw = inb + (w * 6) * INP;
#pragma unroll
            for (int e = 0; e < 6; e++)
#pragma unroll
                for (int u = 0; u < 4; u++) {
                    int j = 32 * u + lane;
                    hidw[e * INP + j] = gelu_t(hadd2(acc[u][e]) + b1s[j]);
                }
        }
        __syncwarp();
        u64 o0[6], o1[6];
#pragma unroll
        for (int e = 0; e < 6; e++) { o0[e] = 0ull; o1[e] = 0ull; }
        {
            const float* hw = inb + (w * 6) * INP;
            const float* wa = w2t + lane * W2P;
            const float* wbp = w2t + (lane + 32) * W2P;
#pragma unroll 2
            for (int k4 = 0; k4 < 32; k4++) {
                ulonglong2 va = *(const ulonglong2*)(wa + 4 * k4);
                ulonglong2 vb = *(const ulonglong2*)(wbp + 4 * k4);
#pragma unroll
                for (int e = 0; e < 6; e++) {
                    ulonglong2 av = *(const ulonglong2*)(hw + e * INP + 4 * k4);
                    FMA2(o0[e], av.x, va.x);
                    FMA2(o0[e], av.y, va.y);
                    FMA2(o1[e], av.x, vb.x);
                    FMA2(o1[e], av.y, vb.y);
                }
            }
        }
#pragma unroll
        for (int e = 0; e < 6; e++) {
            int nid = nbase + w * 6 + e;
            int nc = nid < Nv ? nid : Nv - 1;
            float h0 = g_h[(size_t)nc * 64 + lane];
            float h1 = g_h[(size_t)nc * 64 + 32 + lane];
            float x0 = h0 + hadd2(o0[e]) + b2s[lane];
            float x1 = h1 + hadd2(o1[e]) + b2s[lane + 32];
            float s = x0 + x1, q = x0 * x0 + x1 * x1;
#pragma unroll
            for (int d = 16; d; d >>= 1) {
                s += __shfl_xor_sync(0xffffffffu, s, d);
                q += __shfl_xor_sync(0xffffffffu, q, d);
            }
            float mu = s * (1.0f / 64.0f);
            float var = q * (1.0f / 64.0f) - mu * mu;
            float inv = rsqrtf(var + 1e-6f);
            if (nid < Nv) {
                g_h[(size_t)nid * 64 + lane]      = (x0 - mu) * inv * lns[lane] + lnb[lane];
                g_h[(size_t)nid * 64 + 32 + lane] = (x1 - mu) * inv * lns[lane + 32] + lnb[lane + 32];
            }
        }
        __syncthreads();
    }
}

// ---------------------------------------------------------------------------
__global__ void decode_kernel(const float* __restrict__ dec_w,
                              const float* __restrict__ dec_b,
                              float* __restrict__ out, int Nv) {
    int gwarp = (blockIdx.x * blockDim.x + threadIdx.x) >> 5;
    int lane = threadIdx.x & 31;
    int nWarps = (gridDim.x * blockDim.x) >> 5;
    for (int n = gwarp; n < Nv; n += nWarps) {
        float h0 = g_h[n * 64 + lane];
        float h1 = g_h[n * 64 + 32 + lane];
        float p[7];
#pragma unroll
        for (int k = 0; k < 7; k++)
            p[k] = h0 * dec_w[lane * 7 + k] + h1 * dec_w[(lane + 32) * 7 + k];
#pragma unroll
        for (int k = 0; k < 7; k++)
#pragma unroll
            for (int d = 16; d; d >>= 1) p[k] += __shfl_xor_sync(0xffffffffu, p[k], d);
        if (lane < 7) out[n * 7 + lane] = p[lane] + dec_b[lane];
    }
}

// ---------------------------------------------------------------------------
extern "C" void kernel_launch(void* const* d_in, const int* in_sizes, int n_in,
                              void* d_out, int out_size) {
    const float* nodes   = (const float*)d_in[0];
    const int*   senders = (const int*)d_in[1];
    const int*   recvrs  = (const int*)d_in[2];
    const float* g       = (const float*)d_in[3];
    const float* embed_w = (const float*)d_in[4];
    const float* embed_b = (const float*)d_in[5];
    const float* ew1f    = (const float*)d_in[6];
    const float* ew1r    = (const float*)d_in[7];
    const float* eb1     = (const float*)d_in[8];
    const float* ew2     = (const float*)d_in[9];
    const float* eb2     = (const float*)d_in[10];
    const float* nw1     = (const float*)d_in[11];
    const float* nb1     = (const float*)d_in[12];
    const float* nw2     = (const float*)d_in[13];
    const float* nb2     = (const float*)d_in[14];
    const float* lnsc    = (const float*)d_in[15];
    const float* lnbi    = (const float*)d_in[16];
    const float* dec_w   = (const float*)d_in[17];
    const float* dec_b   = (const float*)d_in[18];
    float* out = (float*)d_out;

    int En = in_sizes[1];
    int Nv = in_sizes[0] / 7;

    size_t sm_pre = (size_t)(128 * 68 * 2 + 16 * 6 * 68) * 4;
    size_t sm_e0  = (size_t)(64 * 132 + 64 + 16 * 6 * 132) * 4;
    size_t sm_e1  = (size_t)(64 * 132 + 64 + 128 * 68 + 16 * 6 * 68 + 16 * 6 * 132) * 4;
    size_t sm_n   = (size_t)(128 * 148 + 64 * 132 + 128 + 64 + 16 + 64 + 64 + 96 * 148) * 4;

    cudaFuncSetAttribute(pre_kernel,
                         cudaFuncAttributeMaxDynamicSharedMemorySize, (int)sm_pre);
    cudaFuncSetAttribute(edge_kernel<false>,
                         cudaFuncAttributeMaxDynamicSharedMemorySize, (int)sm_e0);
    cudaFuncSetAttribute(edge_kernel<true>,
                         cudaFuncAttributeMaxDynamicSharedMemorySize, (int)sm_e1);
    cudaFuncSetAttribute(node_kernel,
                         cudaFuncAttributeMaxDynamicSharedMemorySize, (int)sm_n);

    const int GRID = 148;
    const int GRID_N = 131;

    embed_kernel<<<(Nv * 64 + 255) / 256, 256>>>(nodes, embed_w, embed_b, Nv);

    for (int t = 0; t < 3; t++) {
        zero_recv_kernel<<<(Nv * 64 + 255) / 256, 256>>>(Nv * 64);
        if (t == 0) {
            // w1f layout rows: [0:64)=s, [64:128)=r, [128:144)=g
            const_kernel<<<1, 128>>>(g, ew1f + 128 * 128, eb1, 16);
            pre_kernel<<<GRID, 512, sm_pre>>>(ew1f, ew1f + 64 * 128, Nv);
            edge_kernel<false><<<GRID, 512, sm_e0>>>(
                senders, recvrs, nullptr, ew2, eb2, En, 1);
        } else {
            // w1rest[t-1] rows: [0:64)=e, [64:128)=s, [128:192)=r, [192:208)=g
            const float* base = ew1r + (size_t)(t - 1) * 208 * 128;
            const_kernel<<<1, 128>>>(g, base + 192 * 128, eb1 + t * 128, 16);
            pre_kernel<<<GRID, 512, sm_pre>>>(base + 64 * 128, base + 128 * 128, Nv);
            edge_kernel<true><<<GRID, 512, sm_e1>>>(
                senders, recvrs, base,
                ew2 + (size_t)t * 128 * 64, eb2 + t * 64, En, (t == 2) ? 0 : 1);
        }
        node_kernel<<<GRID_N, 512, sm_n>>>(
            g, nw1 + (size_t)t * 144 * 128, nb1 + t * 128,
            nw2 + (size_t)t * 128 * 64, nb2 + t * 64,
            lnsc + t * 64, lnbi + t * 64, Nv);
    }

    decode_kernel<<<208, 256>>>(dec_w, dec_b, out, Nv);
}